// round 11
// baseline (speedup 1.0000x reference)
#include <cuda_runtime.h>
#include <cuda_bf16.h>
#include <cstdint>

#define B_  16
#define LQ_ 2048
#define S_  2048
#define D_  1024
#define K3QK 3072    // 3*D
#define K3A  6144    // 3*S == 3*LQ

// ------------- scratch (__device__ globals = allocation-guard-safe) -------------
static __device__ __nv_bfloat16 g_qs  [(size_t)B_ * LQ_ * K3QK];  // Q split  A-role [h|h|l]
static __device__ __nv_bfloat16 g_ks  [(size_t)B_ * S_  * K3QK];  // Kc split B-role [h|l|h]
static __device__ __nv_bfloat16 g_vts [(size_t)B_ * D_  * K3A];   // Vc^T split B-role
static __device__ __nv_bfloat16 g_aws [(size_t)B_ * LQ_ * K3A];   // awc split A-role
static __device__ __nv_bfloat16 g_awts[(size_t)B_ * S_  * K3A];   // awc^T split A-role
static __device__ __nv_bfloat16 g_o1ts[(size_t)B_ * D_  * K3A];   // out1^T split B-role
static __device__ float         g_awc [(size_t)B_ * LQ_ * S_];    // compacted scores/probs
static __device__ int           g_pos [B_ * S_];
static __device__ int           g_idx [B_ * S_];
static __device__ int           g_scnt[B_];
static __device__ int           g_sp  [B_];

// ------------- PTX helpers -------------
__device__ __forceinline__ uint32_t smem_u32(const void* p) {
    uint32_t a;
    asm("{ .reg .u64 t; cvta.to.shared.u64 t, %1; cvt.u32.u64 %0, t; }" : "=r"(a) : "l"(p));
    return a;
}
#define CP_ASYNC16(dst, src) \
    asm volatile("cp.async.cg.shared.global [%0], [%1], 16;" :: "r"(dst), "l"(src) : "memory")
#define CP_COMMIT() asm volatile("cp.async.commit_group;" ::: "memory")
#define CP_WAIT1()  asm volatile("cp.async.wait_group 1;" ::: "memory")
#define CP_WAIT0()  asm volatile("cp.async.wait_group 0;" ::: "memory")

__device__ __forceinline__ void ldsm_x4(uint32_t& r0, uint32_t& r1, uint32_t& r2,
                                        uint32_t& r3, uint32_t addr) {
    asm volatile("ldmatrix.sync.aligned.m8n8.x4.shared.b16 {%0,%1,%2,%3}, [%4];"
                 : "=r"(r0), "=r"(r1), "=r"(r2), "=r"(r3) : "r"(addr));
}
__device__ __forceinline__ void mma_bf16(float* c, uint32_t a0, uint32_t a1,
                                         uint32_t a2, uint32_t a3,
                                         uint32_t b0, uint32_t b1) {
    asm volatile(
        "mma.sync.aligned.m16n8k16.row.col.f32.bf16.bf16.f32 "
        "{%0,%1,%2,%3}, {%4,%5,%6,%7}, {%8,%9}, {%0,%1,%2,%3};"
        : "+f"(c[0]), "+f"(c[1]), "+f"(c[2]), "+f"(c[3])
        : "r"(a0), "r"(a1), "r"(a2), "r"(a3), "r"(b0), "r"(b1));
}

// Stage = A 16KB + B 32KB. 3 stages. Epilogue slab (<=135168B) reuses stages.
static constexpr int STAGE   = 49152;
static constexpr int SMEM_SZ = 1024 + 3 * STAGE;   // 148480 < 227KB

// ------------- mma.sync GEMM: C[M,N] = scale * A[M,K] @ B[N,K]^T -------------
// CTA 128x256, 512 threads, 16 warps (4m x 4n), warp tile 32x64, 64-K chunks,
// SW128 xor swizzle, 3-stage cp.async ring, one barrier per chunk.
// MODE 0: N-compact (exit bn>=SP), K = ld, fp32 C at ldc.
// MODE 1: K = 3*SP runtime, pitch ld; bf16 [h|l|h] transposed epi into Tg.
// MODE 2: M-compact (exit bm>=SP), K = ld; fp32 rows scattered via idx (r < Sc).
template<int MODE>
__global__ void __launch_bounds__(512, 1) gemm_mma(
    const __nv_bfloat16* __restrict__ Ag,
    const __nv_bfloat16* __restrict__ Bg,
    float* __restrict__ Cg, __nv_bfloat16* __restrict__ Tg,
    int ld, int ldc, size_t sA, size_t sB, size_t sOut, float scale,
    const int* __restrict__ scnt, const int* __restrict__ sptab,
    const int* __restrict__ idxb)
{
    const int bz = blockIdx.z;
    const int SP = sptab[bz];
    const int bm = blockIdx.y * 128;
    const int bn = blockIdx.x * 256;
    if (MODE == 0 && bn >= SP) return;
    if (MODE == 2 && bm >= SP) return;
    const int K3 = (MODE == 1) ? 3 * SP : ld;

    extern __shared__ char dsm[];
    const uint32_t raw  = smem_u32(dsm);
    const uint32_t base = (raw + 1023u) & ~1023u;
    char* sm = dsm + (base - raw);

    const int tid  = threadIdx.x;
    const int wid  = tid >> 5;
    const int lane = tid & 31;
    const __nv_bfloat16* A  = Ag + bz * sA;
    const __nv_bfloat16* Bp = Bg + bz * sB;

    const int wm = (wid & 3) * 32;         // 4 m-warps
    const int wn = (wid >> 2) * 64;        // 4 n-warps

    float acc[2][8][4];
    #pragma unroll
    for (int i = 0; i < 2; ++i)
        #pragma unroll
        for (int j = 0; j < 8; ++j)
            #pragma unroll
            for (int r = 0; r < 4; ++r) acc[i][j][r] = 0.f;

    const int lra = tid >> 2;              // A row 0..127
    const int ca  = tid & 3;               // A c16 base: {ca, ca+4}
    const int lrb = tid >> 1;              // B row 0..255
    const int cb  = (tid & 1) << 2;        // B c16 base: cb..cb+3
    const int NT  = K3 >> 6;

    auto load_chunk = [&](int kt) {
        const int kc = kt << 6;
        const uint32_t ab = base + (kt % 3) * STAGE;
        const uint32_t bb = ab + 16384;
        const __nv_bfloat16* arow = A  + (size_t)(bm + lra) * ld + kc;
        #pragma unroll
        for (int c = 0; c < 2; ++c) {
            int c16 = ca + c * 4;
            uint32_t sw = (uint32_t)((c16 ^ (lra & 7)) << 4);
            CP_ASYNC16(ab + (uint32_t)(lra << 7) + sw, arow + (c16 << 3));
        }
        const __nv_bfloat16* brow = Bp + (size_t)(bn + lrb) * ld + kc;
        #pragma unroll
        for (int c = 0; c < 4; ++c) {
            int c16 = cb + c;
            uint32_t sw = (uint32_t)((c16 ^ (lrb & 7)) << 4);
            CP_ASYNC16(bb + (uint32_t)(lrb << 7) + sw, brow + (c16 << 3));
        }
        CP_COMMIT();
    };

    load_chunk(0);
    load_chunk(1);

    for (int kt = 0; kt < NT; ++kt) {
        if (kt + 1 < NT) CP_WAIT1();
        else             CP_WAIT0();
        __syncthreads();
        if (kt + 2 < NT) load_chunk(kt + 2);

        const uint32_t ab = base + (kt % 3) * STAGE;
        const uint32_t bb = ab + 16384;
        const int t4 = lane >> 3;

        #pragma unroll
        for (int ks = 0; ks < 4; ++ks) {
            uint32_t Af[2][4];
            #pragma unroll
            for (int mt = 0; mt < 2; ++mt) {
                int row = wm + mt * 16 + ((t4 & 1) << 3) + (lane & 7);
                int c16 = ks * 2 + (t4 >> 1);
                uint32_t addr = ab + (uint32_t)(row << 7)
                              + (uint32_t)((c16 ^ (row & 7)) << 4);
                ldsm_x4(Af[mt][0], Af[mt][1], Af[mt][2], Af[mt][3], addr);
            }
            uint32_t Bf[4][4];   // 4 n16 groups: [b0 lo][b1 lo][b0 hi][b1 hi]
            #pragma unroll
            for (int gt = 0; gt < 4; ++gt) {
                int row = wn + gt * 16 + ((t4 >> 1) << 3) + (lane & 7);
                int c16 = ks * 2 + (t4 & 1);
                uint32_t addr = bb + (uint32_t)(row << 7)
                              + (uint32_t)((c16 ^ (row & 7)) << 4);
                ldsm_x4(Bf[gt][0], Bf[gt][1], Bf[gt][2], Bf[gt][3], addr);
            }
            #pragma unroll
            for (int mt = 0; mt < 2; ++mt)
                #pragma unroll
                for (int ng = 0; ng < 8; ++ng) {
                    const uint32_t* bg = Bf[ng >> 1];
                    mma_bf16(acc[mt][ng],
                             Af[mt][0], Af[mt][1], Af[mt][2], Af[mt][3],
                             bg[(ng & 1) * 2], bg[(ng & 1) * 2 + 1]);
                }
        }
    }
    __syncthreads();

    const int qr = lane >> 2;
    const int qc = (lane & 3) << 1;

    if (MODE == 0 || MODE == 2) {
        float* slab = reinterpret_cast<float*>(sm);   // [m][n] pitch 264
        #pragma unroll
        for (int mt = 0; mt < 2; ++mt)
            #pragma unroll
            for (int ng = 0; ng < 8; ++ng) {
                int m = wm + mt * 16 + qr;
                int n = wn + ng * 8 + qc;
                float* p0 = slab + (size_t)m * 264 + n;
                p0[0] = acc[mt][ng][0] * scale;
                p0[1] = acc[mt][ng][1] * scale;
                float* p1 = p0 + 8 * 264;
                p1[0] = acc[mt][ng][2] * scale;
                p1[1] = acc[mt][ng][3] * scale;
            }
        __syncthreads();
        float* Cb = Cg + bz * sOut;
        const int Sc = (MODE == 2) ? scnt[bz] : 0;
        #pragma unroll
        for (int it = 0; it < 16; ++it) {
            int idx = tid + (it << 9);
            int r = idx >> 6, c = (idx & 63) << 2;
            float4 v = *reinterpret_cast<float4*>(slab + (size_t)r * 264 + c);
            if (MODE == 0) {
                *reinterpret_cast<float4*>(Cb + (size_t)(bm + r) * ldc + bn + c) = v;
            } else {
                int gr = bm + r;
                if (gr < Sc) {
                    int trow = idxb[bz * S_ + gr];
                    *reinterpret_cast<float4*>(Cb + (size_t)trow * ldc + bn + c) = v;
                }
            }
        }
    } else {
        float* slab = reinterpret_cast<float*>(sm);   // [n][m] pitch 132
        #pragma unroll
        for (int mt = 0; mt < 2; ++mt)
            #pragma unroll
            for (int ng = 0; ng < 8; ++ng) {
                int m = wm + mt * 16 + qr;
                int n = wn + ng * 8 + qc;
                slab[(size_t)n * 132 + m]           = acc[mt][ng][0];
                slab[(size_t)(n + 1) * 132 + m]     = acc[mt][ng][1];
                slab[(size_t)n * 132 + m + 8]       = acc[mt][ng][2];
                slab[(size_t)(n + 1) * 132 + m + 8] = acc[mt][ng][3];
            }
        __syncthreads();
        __nv_bfloat16* T = Tg + bz * sOut;
        #pragma unroll
        for (int it = 0; it < 16; ++it) {
            int idx = tid + (it << 9);          // 8192 (n, m-chunk4) pairs
            int n = idx >> 5, mc = (idx & 31) << 2;
            float4 v = *reinterpret_cast<float4*>(slab + (size_t)n * 132 + mc);
            float xs[4] = {v.x, v.y, v.z, v.w};
            __align__(8) __nv_bfloat16 h[4], l[4];
            #pragma unroll
            for (int i = 0; i < 4; ++i) {
                h[i] = __float2bfloat16(xs[i]);
                l[i] = __float2bfloat16(xs[i] - __bfloat162float(h[i]));
            }
            __nv_bfloat16* dst = T + (size_t)(bn + n) * K3A + bm + mc;
            *reinterpret_cast<uint2*>(dst)           = *reinterpret_cast<uint2*>(h);
            *reinterpret_cast<uint2*>(dst + LQ_)     = *reinterpret_cast<uint2*>(l);
            *reinterpret_cast<uint2*>(dst + 2 * LQ_) = *reinterpret_cast<uint2*>(h);
        }
    }
}

// ------------- mask prefix scan: pos, idx, Sc, SP per batch -------------
__global__ void __launch_bounds__(256) scan_mask(
    const int* __restrict__ mask, int* __restrict__ pos, int* __restrict__ idxb,
    int* __restrict__ scnt, int* __restrict__ sptab)
{
    const int b = blockIdx.x;
    const int* mp = mask + b * S_;
    const int t = threadIdx.x;
    __shared__ int part[256];
    int loc[8], sum = 0;
    #pragma unroll
    for (int i = 0; i < 8; ++i) { loc[i] = mp[t * 8 + i]; sum += loc[i]; }
    part[t] = sum;
    __syncthreads();
    for (int off = 1; off < 256; off <<= 1) {
        int v = (t >= off) ? part[t - off] : 0;
        __syncthreads();
        part[t] += v;
        __syncthreads();
    }
    int run = part[t] - sum;
    #pragma unroll
    for (int i = 0; i < 8; ++i) {
        int s = t * 8 + i;
        pos[b * S_ + s] = run;
        if (loc[i]) { idxb[b * S_ + run] = s; ++run; }
    }
    if (t == 255) {
        scnt[b]  = run;
        sptab[b] = (run + 127) & ~127;
    }
}

// ------------- Q split A-role [h|h|l] -------------
__global__ void __launch_bounds__(256) split_rows_q(
    const float* __restrict__ in, __nv_bfloat16* __restrict__ out)
{
    size_t idx = (size_t)blockIdx.x * 256 + threadIdx.x;
    size_t row = idx >> 8;
    int    c   = (int)(idx & 255) << 2;
    float4 v = *reinterpret_cast<const float4*>(in + row * D_ + c);
    float xs[4] = {v.x, v.y, v.z, v.w};
    __align__(8) __nv_bfloat16 h[4], l[4];
    #pragma unroll
    for (int i = 0; i < 4; ++i) {
        h[i] = __float2bfloat16(xs[i]);
        l[i] = __float2bfloat16(xs[i] - __bfloat162float(h[i]));
    }
    __nv_bfloat16* o = out + row * (size_t)K3QK + c;
    *reinterpret_cast<uint2*>(o)          = *reinterpret_cast<uint2*>(h);
    *reinterpret_cast<uint2*>(o + D_)     = *reinterpret_cast<uint2*>(h);
    *reinterpret_cast<uint2*>(o + 2 * D_) = *reinterpret_cast<uint2*>(l);
}

// ------------- K gather+split B-role [h|l|h] -------------
__global__ void __launch_bounds__(256) gather_split_k(
    const float* __restrict__ k, __nv_bfloat16* __restrict__ out,
    const int* __restrict__ idxb, const int* __restrict__ scnt,
    const int* __restrict__ sptab)
{
    const int b = blockIdx.y, j = blockIdx.x;
    if (j >= sptab[b]) return;
    const int t = threadIdx.x, c = t << 2;
    __nv_bfloat16* o = out + ((size_t)b * S_ + j) * K3QK + c;
    __align__(8) __nv_bfloat16 h[4], l[4];
    if (j < scnt[b]) {
        const float* src = k + ((size_t)b * S_ + idxb[b * S_ + j]) * D_ + c;
        float4 v = *reinterpret_cast<const float4*>(src);
        float xs[4] = {v.x, v.y, v.z, v.w};
        #pragma unroll
        for (int i = 0; i < 4; ++i) {
            h[i] = __float2bfloat16(xs[i]);
            l[i] = __float2bfloat16(xs[i] - __bfloat162float(h[i]));
        }
    } else {
        #pragma unroll
        for (int i = 0; i < 4; ++i) { h[i] = __float2bfloat16(0.f); l[i] = h[i]; }
    }
    *reinterpret_cast<uint2*>(o)          = *reinterpret_cast<uint2*>(h);
    *reinterpret_cast<uint2*>(o + D_)     = *reinterpret_cast<uint2*>(l);
    *reinterpret_cast<uint2*>(o + 2 * D_) = *reinterpret_cast<uint2*>(h);
}

// ------------- V gather + transpose + split B-role [h|l|h] -------------
__global__ void __launch_bounds__(256) gather_tsplit_v(
    const float* __restrict__ v, __nv_bfloat16* __restrict__ out,
    const int* __restrict__ idxb, const int* __restrict__ scnt,
    const int* __restrict__ sptab)
{
    const int b  = blockIdx.z;
    const int SP = sptab[b], Sc = scnt[b];
    const int j0 = blockIdx.x * 32;
    if (j0 >= SP) return;
    const int d0 = blockIdx.y * 32;
    const float* ip = v + (size_t)b * S_ * D_;
    __nv_bfloat16* op = out + (size_t)b * D_ * K3A;
    __shared__ float tile[32][33];
    const int tx = threadIdx.x & 31, ty = threadIdx.x >> 5;
    #pragma unroll
    for (int i = 0; i < 4; ++i) {
        int jr = j0 + ty + i * 8;
        float val = 0.f;
        if (jr < Sc) val = ip[(size_t)idxb[b * S_ + jr] * D_ + d0 + tx];
        tile[ty + i * 8][tx] = val;
    }
    __syncthreads();
    #pragma unroll
    for (int i = 0; i < 4; ++i) {
        int cc = ty + i * 8;
        float x = tile[tx][cc];
        __nv_bfloat16 h = __float2bfloat16(x);
        __nv_bfloat16 l = __float2bfloat16(x - __bfloat162float(h));
        __nv_bfloat16* o = op + (size_t)(d0 + cc) * K3A + j0 + tx;
        o[0]      = h;
        o[SP]     = l;
        o[2 * SP] = h;
    }
}

// ------------- softmax over compacted row + full-aw scatter + A-role split ---
__global__ void __launch_bounds__(256) softmax_compact(
    float* __restrict__ awc, float* __restrict__ aw, const int* __restrict__ mask,
    __nv_bfloat16* __restrict__ aws, const int* __restrict__ pos,
    const int* __restrict__ scnt, const int* __restrict__ sptab)
{
    const int row = blockIdx.x;
    const int b   = row >> 11;
    const int Sc  = scnt[b], SP = sptab[b];
    float*         cp = awc + (size_t)row * S_;
    float*         rp = aw  + (size_t)row * S_;
    __nv_bfloat16* ap = aws + (size_t)row * K3A;
    const int*     mp = mask + b * S_;
    const int*     pp = pos  + b * S_;
    const int t = threadIdx.x;
    const float NEG_INF = __int_as_float(0xff800000);

    __shared__ float parr[2048];
    __shared__ float smax[8], ssum[8];

    float vv[8];
    float mx = NEG_INF;
    #pragma unroll
    for (int i = 0; i < 8; ++i) {
        int j = t + (i << 8);
        vv[i] = (j < Sc) ? cp[j] : NEG_INF;
        mx = fmaxf(mx, vv[i]);
    }
    #pragma unroll
    for (int off = 16; off > 0; off >>= 1)
        mx = fmaxf(mx, __shfl_xor_sync(0xffffffffu, mx, off));
    if ((t & 31) == 0) smax[t >> 5] = mx;
    __syncthreads();
    float rmax = smax[0];
    #pragma unroll
    for (int i = 1; i < 8; ++i) rmax = fmaxf(rmax, smax[i]);

    float e[8], sum = 0.f;
    #pragma unroll
    for (int i = 0; i < 8; ++i) {
        int j = t + (i << 8);
        e[i] = (j < Sc) ? __expf(vv[i] - rmax) : 0.f;
        sum += e[i];
    }
    #pragma unroll
    for (int off = 16; off > 0; off >>= 1)
        sum += __shfl_xor_sync(0xffffffffu, sum, off);
    if ((t & 31) == 0) ssum[t >> 5] = sum;
    __syncthreads();
    float rsum = 0.f;
    #pragma unroll
    for (int i = 0; i < 8; ++i) rsum += ssum[i];
    const float inv = 1.f / rsum;

    #pragma unroll
    for (int i = 0; i < 8; ++i) {
        int j = t + (i << 8);
        if (j < SP) {
            float p = e[i] * inv;
            cp[j]   = p;
            parr[j] = p;
            __nv_bfloat16 h = __float2bfloat16(p);
            __nv_bfloat16 l = __float2bfloat16(p - __bfloat162float(h));
            ap[j]          = h;
            ap[SP + j]     = h;
            ap[2 * SP + j] = l;
        }
    }
    __syncthreads();
    #pragma unroll
    for (int i = 0; i < 8; ++i) {
        int s = t + (i << 8);
        rp[s] = mp[s] ? parr[pp[s]] : 0.f;
    }
}

// ------------- transpose+split awc -> awts A-role [h|h|l] -------------
__global__ void __launch_bounds__(256) tsplit_awc(
    const float* __restrict__ awc, __nv_bfloat16* __restrict__ out,
    const int* __restrict__ sptab)
{
    const int b  = blockIdx.z;
    const int c0 = blockIdx.y * 32;
    if (c0 >= sptab[b]) return;
    const int r0 = blockIdx.x * 32;
    const float* ip = awc + (size_t)b * LQ_ * S_;
    __nv_bfloat16* op = out + (size_t)b * S_ * K3A;
    __shared__ float tile[32][33];
    const int tx = threadIdx.x & 31, ty = threadIdx.x >> 5;
    #pragma unroll
    for (int i = 0; i < 4; ++i)
        tile[ty + i * 8][tx] = ip[(size_t)(r0 + ty + i * 8) * S_ + c0 + tx];
    __syncthreads();
    #pragma unroll
    for (int i = 0; i < 4; ++i) {
        int cc = ty + i * 8;
        float x = tile[tx][cc];
        __nv_bfloat16 h = __float2bfloat16(x);
        __nv_bfloat16 l = __float2bfloat16(x - __bfloat162float(h));
        __nv_bfloat16* o = op + (size_t)(c0 + cc) * K3A + r0 + tx;
        o[0]       = h;
        o[LQ_]     = h;
        o[2 * LQ_] = l;
    }
}

// ------------- zero output rows where mask == 0 -------------
__global__ void __launch_bounds__(256) zero_masked(
    float* __restrict__ out, const int* __restrict__ mask)
{
    const int b = blockIdx.y, s = blockIdx.x;
    if (mask[b * S_ + s]) return;
    float* r = out + ((size_t)b * S_ + s) * D_;
    float4 z = make_float4(0.f, 0.f, 0.f, 0.f);
    *reinterpret_cast<float4*>(r + (threadIdx.x << 2)) = z;
}

extern "C" void kernel_launch(void* const* d_in, const int* in_sizes, int n_in,
                              void* d_out, int out_size)
{
    const float* q    = (const float*)d_in[0];
    const float* kk   = (const float*)d_in[1];
    const float* v    = (const float*)d_in[2];
    const int*   mask = (const int*)  d_in[3];

    float* out = (float*)d_out;                       // output [B,S,D]
    float* aw  = out + (size_t)B_ * S_ * D_;          // attention_weights [B,LQ,S]

    void* p;
    cudaGetSymbolAddress(&p, g_qs);   __nv_bfloat16* qs   = (__nv_bfloat16*)p;
    cudaGetSymbolAddress(&p, g_ks);   __nv_bfloat16* ks   = (__nv_bfloat16*)p;
    cudaGetSymbolAddress(&p, g_vts);  __nv_bfloat16* vts  = (__nv_bfloat16*)p;
    cudaGetSymbolAddress(&p, g_aws);  __nv_bfloat16* aws  = (__nv_bfloat16*)p;
    cudaGetSymbolAddress(&p, g_awts); __nv_bfloat16* awts = (__nv_bfloat16*)p;
    cudaGetSymbolAddress(&p, g_o1ts); __nv_bfloat16* o1ts = (__nv_bfloat16*)p;
    cudaGetSymbolAddress(&p, g_awc);  float* awc  = (float*)p;
    cudaGetSymbolAddress(&p, g_pos);  int*   pos  = (int*)p;
    cudaGetSymbolAddress(&p, g_idx);  int*   idxb = (int*)p;
    cudaGetSymbolAddress(&p, g_scnt); int*   scnt = (int*)p;
    cudaGetSymbolAddress(&p, g_sp);   int*   sp   = (int*)p;

    cudaFuncSetAttribute(gemm_mma<0>, cudaFuncAttributeMaxDynamicSharedMemorySize, SMEM_SZ);
    cudaFuncSetAttribute(gemm_mma<1>, cudaFuncAttributeMaxDynamicSharedMemorySize, SMEM_SZ);
    cudaFuncSetAttribute(gemm_mma<2>, cudaFuncAttributeMaxDynamicSharedMemorySize, SMEM_SZ);

    // 0) mask scan
    scan_mask<<<B_, 256>>>(mask, pos, idxb, scnt, sp);

    // 1) operand prep
    split_rows_q<<<(int)(((size_t)B_ * LQ_ * D_ / 4) / 256), 256>>>(q, qs);
    gather_split_k<<<dim3(S_, B_), 256>>>(kk, ks, idxb, scnt, sp);
    gather_tsplit_v<<<dim3(S_ / 32, D_ / 32, B_), 256>>>(v, vts, idxb, scnt, sp);

    // 2) scores_c = Q @ Kc^T / 32 -> awc (compact N)
    gemm_mma<0><<<dim3(S_ / 256, LQ_ / 128, B_), 512, SMEM_SZ>>>(
        qs, ks, awc, nullptr, K3QK, S_,
        (size_t)LQ_ * K3QK, (size_t)S_ * K3QK, (size_t)LQ_ * S_, 0.03125f,
        scnt, sp, idxb);

    // 3) softmax on compacted rows; scatter full aw; A-role split
    softmax_compact<<<B_ * LQ_, 256>>>(awc, aw, mask, aws, pos, scnt, sp);

    // 4) awc^T split (A-role, compacted rows)
    tsplit_awc<<<dim3(LQ_ / 32, S_ / 32, B_), 256>>>(awc, awts, sp);

    // 5) out1 = awc @ Vc (K = 3*SP) -> o1ts (bf16 split-T, B-role)
    gemm_mma<1><<<dim3(D_ / 256, LQ_ / 128, B_), 512, SMEM_SZ>>>(
        aws, vts, nullptr, o1ts, K3A, 0,
        (size_t)LQ_ * K3A, (size_t)D_ * K3A, (size_t)D_ * K3A, 1.0f,
        scnt, sp, idxb);

    // 6) zero masked output rows; compute unmasked rows scattered via idx
    zero_masked<<<dim3(S_, B_), 256>>>(out, mask);
    gemm_mma<2><<<dim3(D_ / 256, S_ / 128, B_), 512, SMEM_SZ>>>(
        awts, o1ts, out, nullptr, K3A, D_,
        (size_t)S_ * K3A, (size_t)D_ * K3A, (size_t)S_ * D_, 1.0f,
        scnt, sp, idxb);
}

// round 12
// speedup vs baseline: 1.2672x; 1.2672x over previous
#include <cuda_runtime.h>
#include <cuda_fp16.h>
#include <cstdint>

#define B_  16
#define LQ_ 2048
#define S_  2048
#define D_  1024
#define K3QK 3072    // 3*D  (GEMM1, 3-term)
#define K2   4096    // 2*S == 2*LQ (GEMM2/3 row pitch, 2-term)

// ------------- scratch (__device__ globals = allocation-guard-safe) -------------
static __device__ __half g_qs  [(size_t)B_ * LQ_ * K3QK];  // Q  A-role [h|h|l] fp16
static __device__ __half g_ks  [(size_t)B_ * S_  * K3QK];  // Kc B-role [h|l|h] fp16
static __device__ __half g_vts [(size_t)B_ * D_  * K2];    // Vc^T B-role [h|h] (dup)
static __device__ __half g_aws [(size_t)B_ * LQ_ * K2];    // awc A-role [h|l]
static __device__ __half g_awts[(size_t)B_ * S_  * K2];    // awc^T A-role [h|l]
static __device__ __half g_o1ts[(size_t)B_ * D_  * K2];    // out1^T B-role [h|h] (dup)
static __device__ float  g_awc [(size_t)B_ * LQ_ * S_];    // compacted scores/probs
static __device__ int    g_pos [B_ * S_];
static __device__ int    g_idx [B_ * S_];
static __device__ int    g_scnt[B_];
static __device__ int    g_sp  [B_];

// ------------- PTX helpers -------------
__device__ __forceinline__ uint32_t smem_u32(const void* p) {
    uint32_t a;
    asm("{ .reg .u64 t; cvta.to.shared.u64 t, %1; cvt.u32.u64 %0, t; }" : "=r"(a) : "l"(p));
    return a;
}
#define CP_ASYNC16(dst, src) \
    asm volatile("cp.async.cg.shared.global [%0], [%1], 16;" :: "r"(dst), "l"(src) : "memory")
#define CP_COMMIT() asm volatile("cp.async.commit_group;" ::: "memory")
#define CP_WAIT1()  asm volatile("cp.async.wait_group 1;" ::: "memory")
#define CP_WAIT0()  asm volatile("cp.async.wait_group 0;" ::: "memory")

__device__ __forceinline__ void ldsm_x4(uint32_t& r0, uint32_t& r1, uint32_t& r2,
                                        uint32_t& r3, uint32_t addr) {
    asm volatile("ldmatrix.sync.aligned.m8n8.x4.shared.b16 {%0,%1,%2,%3}, [%4];"
                 : "=r"(r0), "=r"(r1), "=r"(r2), "=r"(r3) : "r"(addr));
}
__device__ __forceinline__ void mma_f16(float* c, uint32_t a0, uint32_t a1,
                                        uint32_t a2, uint32_t a3,
                                        uint32_t b0, uint32_t b1) {
    asm volatile(
        "mma.sync.aligned.m16n8k16.row.col.f32.f16.f16.f32 "
        "{%0,%1,%2,%3}, {%4,%5,%6,%7}, {%8,%9}, {%0,%1,%2,%3};"
        : "+f"(c[0]), "+f"(c[1]), "+f"(c[2]), "+f"(c[3])
        : "r"(a0), "r"(a1), "r"(a2), "r"(a3), "r"(b0), "r"(b1));
}
__device__ __forceinline__ void hsplit(float x, __half& h, __half& l) {
    h = __float2half_rn(x);
    l = __float2half_rn(x - __half2float(h));
}

static constexpr int STAGE   = 32768;
static constexpr int SMEM_SZ = 1024 + 3 * STAGE;

// ------------- mma.sync GEMM: C[M,N] = scale * A[M,K] @ B[N,K]^T -------------
// CTA 128x128, 8 warps 64x32, 64-K chunks, SW128 xor swizzle, 3-stage ring.
// MODE 0 (G1): N-compact (exit bn>=SP), K = ld (=3072), fp32 C at ldc.
// MODE 1 (G2): K = 2*SP runtime, pitch ld (=K2); [h|h] dup epi into Tg pitch K2.
// MODE 2 (G3): M-compact (exit bm>=SP), K = ld (=K2); rows scattered via idx.
template<int MODE>
__global__ void __launch_bounds__(256, 2) gemm_mma(
    const __half* __restrict__ Ag,
    const __half* __restrict__ Bg,
    float* __restrict__ Cg, __half* __restrict__ Tg,
    int ld, int ldc, size_t sA, size_t sB, size_t sOut, float scale,
    const int* __restrict__ scnt, const int* __restrict__ sptab,
    const int* __restrict__ idxb)
{
    const int bz = blockIdx.z;
    const int SP = sptab[bz];
    const int bm = blockIdx.y * 128;
    const int bn = blockIdx.x * 128;
    if (MODE == 0 && bn >= SP) return;
    if (MODE == 2 && bm >= SP) return;
    const int K3 = (MODE == 1) ? 2 * SP : ld;

    extern __shared__ char dsm[];
    const uint32_t raw  = smem_u32(dsm);
    const uint32_t base = (raw + 1023u) & ~1023u;
    char* sm = dsm + (base - raw);

    const int tid  = threadIdx.x;
    const int wid  = tid >> 5;
    const int lane = tid & 31;
    const __half* A  = Ag + bz * sA;
    const __half* Bp = Bg + bz * sB;

    const int wm = (wid & 1) * 64;
    const int wn = (wid >> 1) * 32;

    float acc[4][4][4];
    #pragma unroll
    for (int i = 0; i < 4; ++i)
        #pragma unroll
        for (int j = 0; j < 4; ++j)
            #pragma unroll
            for (int r = 0; r < 4; ++r) acc[i][j][r] = 0.f;

    const int lr  = tid >> 1;
    const int lc0 = (tid & 1) << 2;
    const int NT  = K3 >> 6;

    auto load_chunk = [&](int kt) {
        const int kc = kt << 6;
        const uint32_t ab = base + (kt % 3) * STAGE;
        const uint32_t bb = ab + 16384;
        const __half* arow = A  + (size_t)(bm + lr) * ld + kc;
        const __half* brow = Bp + (size_t)(bn + lr) * ld + kc;
        #pragma unroll
        for (int c = 0; c < 4; ++c) {
            int c16 = lc0 + c;
            uint32_t sw = (uint32_t)((c16 ^ (lr & 7)) << 4);
            CP_ASYNC16(ab + (uint32_t)(lr << 7) + sw, arow + (c16 << 3));
            CP_ASYNC16(bb + (uint32_t)(lr << 7) + sw, brow + (c16 << 3));
        }
        CP_COMMIT();
    };

    load_chunk(0);
    load_chunk(1);

    for (int kt = 0; kt < NT; ++kt) {
        if (kt + 1 < NT) CP_WAIT1();
        else             CP_WAIT0();
        __syncthreads();
        if (kt + 2 < NT) load_chunk(kt + 2);

        const uint32_t ab = base + (kt % 3) * STAGE;
        const uint32_t bb = ab + 16384;
        const int t4 = lane >> 3;

        #pragma unroll
        for (int ks = 0; ks < 4; ++ks) {
            uint32_t Af[4][4];
            #pragma unroll
            for (int mt = 0; mt < 4; ++mt) {
                int row = wm + mt * 16 + ((t4 & 1) << 3) + (lane & 7);
                int c16 = ks * 2 + (t4 >> 1);
                uint32_t addr = ab + (uint32_t)(row << 7)
                              + (uint32_t)((c16 ^ (row & 7)) << 4);
                ldsm_x4(Af[mt][0], Af[mt][1], Af[mt][2], Af[mt][3], addr);
            }
            uint32_t Bf[2][4];
            #pragma unroll
            for (int gt = 0; gt < 2; ++gt) {
                int row = wn + gt * 16 + ((t4 >> 1) << 3) + (lane & 7);
                int c16 = ks * 2 + (t4 & 1);
                uint32_t addr = bb + (uint32_t)(row << 7)
                              + (uint32_t)((c16 ^ (row & 7)) << 4);
                ldsm_x4(Bf[gt][0], Bf[gt][1], Bf[gt][2], Bf[gt][3], addr);
            }
            #pragma unroll
            for (int mt = 0; mt < 4; ++mt)
                #pragma unroll
                for (int ng = 0; ng < 4; ++ng) {
                    const uint32_t* bg = Bf[ng >> 1];
                    mma_f16(acc[mt][ng],
                            Af[mt][0], Af[mt][1], Af[mt][2], Af[mt][3],
                            bg[(ng & 1) * 2], bg[(ng & 1) * 2 + 1]);
                }
        }
    }
    __syncthreads();

    const int qr = lane >> 2;
    const int qc = (lane & 3) << 1;

    if (MODE == 0 || MODE == 2) {
        float* slab = reinterpret_cast<float*>(sm);   // [m][n] pitch 132
        #pragma unroll
        for (int mt = 0; mt < 4; ++mt)
            #pragma unroll
            for (int ng = 0; ng < 4; ++ng) {
                int m = wm + mt * 16 + qr;
                int n = wn + ng * 8 + qc;
                float* p0 = slab + (size_t)m * 132 + n;
                p0[0] = acc[mt][ng][0] * scale;
                p0[1] = acc[mt][ng][1] * scale;
                float* p1 = p0 + 8 * 132;
                p1[0] = acc[mt][ng][2] * scale;
                p1[1] = acc[mt][ng][3] * scale;
            }
        __syncthreads();
        float* Cb = Cg + bz * sOut;
        const int Sc = (MODE == 2) ? scnt[bz] : 0;
        #pragma unroll
        for (int it = 0; it < 16; ++it) {
            int idx = tid + (it << 8);
            int r = idx >> 5, c = (idx & 31) << 2;
            float4 v = *reinterpret_cast<float4*>(slab + (size_t)r * 132 + c);
            if (MODE == 0) {
                *reinterpret_cast<float4*>(Cb + (size_t)(bm + r) * ldc + bn + c) = v;
            } else {
                int gr = bm + r;
                if (gr < Sc) {
                    int trow = idxb[bz * S_ + gr];
                    *reinterpret_cast<float4*>(Cb + (size_t)trow * ldc + bn + c) = v;
                }
            }
        }
    } else {
        float* slab = reinterpret_cast<float*>(sm);   // [n][m] pitch 132
        #pragma unroll
        for (int mt = 0; mt < 4; ++mt)
            #pragma unroll
            for (int ng = 0; ng < 4; ++ng) {
                int m = wm + mt * 16 + qr;
                int n = wn + ng * 8 + qc;
                slab[(size_t)n * 132 + m]           = acc[mt][ng][0];
                slab[(size_t)(n + 1) * 132 + m]     = acc[mt][ng][1];
                slab[(size_t)n * 132 + m + 8]       = acc[mt][ng][2];
                slab[(size_t)(n + 1) * 132 + m + 8] = acc[mt][ng][3];
            }
        __syncthreads();
        __half* T = Tg + bz * sOut;
        #pragma unroll
        for (int it = 0; it < 16; ++it) {
            int idx = tid + (it << 8);
            int n = idx >> 5, mc = (idx & 31) << 2;
            float4 v = *reinterpret_cast<float4*>(slab + (size_t)n * 132 + mc);
            float xs[4] = {v.x, v.y, v.z, v.w};
            __align__(8) __half h[4];
            #pragma unroll
            for (int i = 0; i < 4; ++i) h[i] = __float2half_rn(xs[i]);
            __half* dst = T + (size_t)(bn + n) * K2 + bm + mc;
            *reinterpret_cast<uint2*>(dst)       = *reinterpret_cast<uint2*>(h);
            *reinterpret_cast<uint2*>(dst + LQ_) = *reinterpret_cast<uint2*>(h);
        }
    }
}

// ------------- mask prefix scan -------------
__global__ void __launch_bounds__(256) scan_mask(
    const int* __restrict__ mask, int* __restrict__ pos, int* __restrict__ idxb,
    int* __restrict__ scnt, int* __restrict__ sptab)
{
    const int b = blockIdx.x;
    const int* mp = mask + b * S_;
    const int t = threadIdx.x;
    __shared__ int part[256];
    int loc[8], sum = 0;
    #pragma unroll
    for (int i = 0; i < 8; ++i) { loc[i] = mp[t * 8 + i]; sum += loc[i]; }
    part[t] = sum;
    __syncthreads();
    for (int off = 1; off < 256; off <<= 1) {
        int v = (t >= off) ? part[t - off] : 0;
        __syncthreads();
        part[t] += v;
        __syncthreads();
    }
    int run = part[t] - sum;
    #pragma unroll
    for (int i = 0; i < 8; ++i) {
        int s = t * 8 + i;
        pos[b * S_ + s] = run;
        if (loc[i]) { idxb[b * S_ + run] = s; ++run; }
    }
    if (t == 255) {
        scnt[b]  = run;
        sptab[b] = (run + 127) & ~127;
    }
}

// ------------- Q split A-role [h|h|l] fp16, pitch 3072 -------------
__global__ void __launch_bounds__(256) split_rows_q(
    const float* __restrict__ in, __half* __restrict__ out)
{
    size_t idx = (size_t)blockIdx.x * 256 + threadIdx.x;
    size_t row = idx >> 8;
    int    c   = (int)(idx & 255) << 2;
    float4 v = *reinterpret_cast<const float4*>(in + row * D_ + c);
    float xs[4] = {v.x, v.y, v.z, v.w};
    __align__(8) __half h[4], l[4];
    #pragma unroll
    for (int i = 0; i < 4; ++i) hsplit(xs[i], h[i], l[i]);
    __half* o = out + row * (size_t)K3QK + c;
    *reinterpret_cast<uint2*>(o)          = *reinterpret_cast<uint2*>(h);
    *reinterpret_cast<uint2*>(o + D_)     = *reinterpret_cast<uint2*>(h);
    *reinterpret_cast<uint2*>(o + 2 * D_) = *reinterpret_cast<uint2*>(l);
}

// ------------- K gather+split B-role [h|l|h] fp16 -------------
__global__ void __launch_bounds__(256) gather_split_k(
    const float* __restrict__ k, __half* __restrict__ out,
    const int* __restrict__ idxb, const int* __restrict__ scnt,
    const int* __restrict__ sptab)
{
    const int b = blockIdx.y, j = blockIdx.x;
    if (j >= sptab[b]) return;
    const int t = threadIdx.x, c = t << 2;
    __half* o = out + ((size_t)b * S_ + j) * K3QK + c;
    __align__(8) __half h[4], l[4];
    if (j < scnt[b]) {
        const float* src = k + ((size_t)b * S_ + idxb[b * S_ + j]) * D_ + c;
        float4 v = *reinterpret_cast<const float4*>(src);
        float xs[4] = {v.x, v.y, v.z, v.w};
        #pragma unroll
        for (int i = 0; i < 4; ++i) hsplit(xs[i], h[i], l[i]);
    } else {
        #pragma unroll
        for (int i = 0; i < 4; ++i) { h[i] = __float2half_rn(0.f); l[i] = h[i]; }
    }
    *reinterpret_cast<uint2*>(o)          = *reinterpret_cast<uint2*>(h);
    *reinterpret_cast<uint2*>(o + D_)     = *reinterpret_cast<uint2*>(l);
    *reinterpret_cast<uint2*>(o + 2 * D_) = *reinterpret_cast<uint2*>(h);
}

// ------------- V gather + transpose B-role [h|h] dup, seg pitch SP -------------
__global__ void __launch_bounds__(256) gather_tsplit_v(
    const float* __restrict__ v, __half* __restrict__ out,
    const int* __restrict__ idxb, const int* __restrict__ scnt,
    const int* __restrict__ sptab)
{
    const int b  = blockIdx.z;
    const int SP = sptab[b], Sc = scnt[b];
    const int j0 = blockIdx.x * 32;
    if (j0 >= SP) return;
    const int d0 = blockIdx.y * 32;
    const float* ip = v + (size_t)b * S_ * D_;
    __half* op = out + (size_t)b * D_ * K2;
    __shared__ float tile[32][33];
    const int tx = threadIdx.x & 31, ty = threadIdx.x >> 5;
    #pragma unroll
    for (int i = 0; i < 4; ++i) {
        int jr = j0 + ty + i * 8;
        float val = 0.f;
        if (jr < Sc) val = ip[(size_t)idxb[b * S_ + jr] * D_ + d0 + tx];
        tile[ty + i * 8][tx] = val;
    }
    __syncthreads();
    #pragma unroll
    for (int i = 0; i < 4; ++i) {
        int cc = ty + i * 8;
        __half h = __float2half_rn(tile[tx][cc]);
        __half* o = op + (size_t)(d0 + cc) * K2 + j0 + tx;
        o[0]  = h;
        o[SP] = h;
    }
}

// ------------- softmax compact + full-aw scatter + A-role [h|l] split -------------
__global__ void __launch_bounds__(256) softmax_compact(
    float* __restrict__ awc, float* __restrict__ aw, const int* __restrict__ mask,
    __half* __restrict__ aws, const int* __restrict__ pos,
    const int* __restrict__ scnt, const int* __restrict__ sptab)
{
    const int row = blockIdx.x;
    const int b   = row >> 11;
    const int Sc  = scnt[b], SP = sptab[b];
    float*      cp = awc + (size_t)row * S_;
    float*      rp = aw  + (size_t)row * S_;
    __half*     ap = aws + (size_t)row * K2;
    const int*  mp = mask + b * S_;
    const int*  pp = pos  + b * S_;
    const int t = threadIdx.x;
    const float NEG_INF = __int_as_float(0xff800000);

    __shared__ float parr[2048];
    __shared__ float smax[8], ssum[8];

    float vv[8];
    float mx = NEG_INF;
    #pragma unroll
    for (int i = 0; i < 8; ++i) {
        int j = t + (i << 8);
        vv[i] = (j < Sc) ? cp[j] : NEG_INF;
        mx = fmaxf(mx, vv[i]);
    }
    #pragma unroll
    for (int off = 16; off > 0; off >>= 1)
        mx = fmaxf(mx, __shfl_xor_sync(0xffffffffu, mx, off));
    if ((t & 31) == 0) smax[t >> 5] = mx;
    __syncthreads();
    float rmax = smax[0];
    #pragma unroll
    for (int i = 1; i < 8; ++i) rmax = fmaxf(rmax, smax[i]);

    float e[8], sum = 0.f;
    #pragma unroll
    for (int i = 0; i < 8; ++i) {
        int j = t + (i << 8);
        e[i] = (j < Sc) ? __expf(vv[i] - rmax) : 0.f;
        sum += e[i];
    }
    #pragma unroll
    for (int off = 16; off > 0; off >>= 1)
        sum += __shfl_xor_sync(0xffffffffu, sum, off);
    if ((t & 31) == 0) ssum[t >> 5] = sum;
    __syncthreads();
    float rsum = 0.f;
    #pragma unroll
    for (int i = 0; i < 8; ++i) rsum += ssum[i];
    const float inv = 1.f / rsum;

    #pragma unroll
    for (int i = 0; i < 8; ++i) {
        int j = t + (i << 8);
        if (j < SP) {
            float p = e[i] * inv;
            cp[j]   = p;
            parr[j] = p;
            __half h, l;
            hsplit(p, h, l);
            ap[j]      = h;
            ap[SP + j] = l;
        }
    }
    __syncthreads();
    #pragma unroll
    for (int i = 0; i < 8; ++i) {
        int s = t + (i << 8);
        rp[s] = mp[s] ? parr[pp[s]] : 0.f;
    }
}

// ------------- transpose+split awc -> awts A-role [h|l], pitch K2 -------------
__global__ void __launch_bounds__(256) tsplit_awc(
    const float* __restrict__ awc, __half* __restrict__ out,
    const int* __restrict__ sptab)
{
    const int b  = blockIdx.z;
    const int c0 = blockIdx.y * 32;
    if (c0 >= sptab[b]) return;
    const int r0 = blockIdx.x * 32;
    const float* ip = awc + (size_t)b * LQ_ * S_;
    __half* op = out + (size_t)b * S_ * K2;
    __shared__ float tile[32][33];
    const int tx = threadIdx.x & 31, ty = threadIdx.x >> 5;
    #pragma unroll
    for (int i = 0; i < 4; ++i)
        tile[ty + i * 8][tx] = ip[(size_t)(r0 + ty + i * 8) * S_ + c0 + tx];
    __syncthreads();
    #pragma unroll
    for (int i = 0; i < 4; ++i) {
        int cc = ty + i * 8;
        __half h, l;
        hsplit(tile[tx][cc], h, l);
        __half* o = op + (size_t)(c0 + cc) * K2 + r0 + tx;
        o[0]   = h;
        o[LQ_] = l;
    }
}

// ------------- zero output rows where mask == 0 -------------
__global__ void __launch_bounds__(256) zero_masked(
    float* __restrict__ out, const int* __restrict__ mask)
{
    const int b = blockIdx.y, s = blockIdx.x;
    if (mask[b * S_ + s]) return;
    float* r = out + ((size_t)b * S_ + s) * D_;
    float4 z = make_float4(0.f, 0.f, 0.f, 0.f);
    *reinterpret_cast<float4*>(r + (threadIdx.x << 2)) = z;
}

extern "C" void kernel_launch(void* const* d_in, const int* in_sizes, int n_in,
                              void* d_out, int out_size)
{
    const float* q    = (const float*)d_in[0];
    const float* kk   = (const float*)d_in[1];
    const float* v    = (const float*)d_in[2];
    const int*   mask = (const int*)  d_in[3];

    float* out = (float*)d_out;                       // output [B,S,D]
    float* aw  = out + (size_t)B_ * S_ * D_;          // attention_weights [B,LQ,S]

    void* p;
    cudaGetSymbolAddress(&p, g_qs);   __half* qs   = (__half*)p;
    cudaGetSymbolAddress(&p, g_ks);   __half* ks   = (__half*)p;
    cudaGetSymbolAddress(&p, g_vts);  __half* vts  = (__half*)p;
    cudaGetSymbolAddress(&p, g_aws);  __half* aws  = (__half*)p;
    cudaGetSymbolAddress(&p, g_awts); __half* awts = (__half*)p;
    cudaGetSymbolAddress(&p, g_o1ts); __half* o1ts = (__half*)p;
    cudaGetSymbolAddress(&p, g_awc);  float* awc  = (float*)p;
    cudaGetSymbolAddress(&p, g_pos);  int*   pos  = (int*)p;
    cudaGetSymbolAddress(&p, g_idx);  int*   idxb = (int*)p;
    cudaGetSymbolAddress(&p, g_scnt); int*   scnt = (int*)p;
    cudaGetSymbolAddress(&p, g_sp);   int*   sp   = (int*)p;

    cudaFuncSetAttribute(gemm_mma<0>, cudaFuncAttributeMaxDynamicSharedMemorySize, SMEM_SZ);
    cudaFuncSetAttribute(gemm_mma<1>, cudaFuncAttributeMaxDynamicSharedMemorySize, SMEM_SZ);
    cudaFuncSetAttribute(gemm_mma<2>, cudaFuncAttributeMaxDynamicSharedMemorySize, SMEM_SZ);

    // 0) mask scan
    scan_mask<<<B_, 256>>>(mask, pos, idxb, scnt, sp);

    // 1) operand prep
    split_rows_q<<<(int)(((size_t)B_ * LQ_ * D_ / 4) / 256), 256>>>(q, qs);
    gather_split_k<<<dim3(S_, B_), 256>>>(kk, ks, idxb, scnt, sp);
    gather_tsplit_v<<<dim3(S_ / 32, D_ / 32, B_), 256>>>(v, vts, idxb, scnt, sp);

    // 2) scores_c = Q @ Kc^T / 32 -> awc  (3-term fp16, N-compact)
    gemm_mma<0><<<dim3(S_ / 128, LQ_ / 128, B_), 256, SMEM_SZ>>>(
        qs, ks, awc, nullptr, K3QK, S_,
        (size_t)LQ_ * K3QK, (size_t)S_ * K3QK, (size_t)LQ_ * S_, 0.03125f,
        scnt, sp, idxb);

    // 3) softmax on compacted rows; scatter full aw; A-role [h|l] split
    softmax_compact<<<B_ * LQ_, 256>>>(awc, aw, mask, aws, pos, scnt, sp);

    // 4) awc^T split (A-role [h|l], compacted rows)
    tsplit_awc<<<dim3(LQ_ / 32, S_ / 32, B_), 256>>>(awc, awts, sp);

    // 5) out1 = awc @ Vc  (2-term, K = 2*SP) -> o1ts ([h|h] dup epi)
    gemm_mma<1><<<dim3(D_ / 128, LQ_ / 128, B_), 256, SMEM_SZ>>>(
        aws, vts, nullptr, o1ts, K2, 0,
        (size_t)LQ_ * K2, (size_t)D_ * K2, (size_t)D_ * K2, 1.0f,
        scnt, sp, idxb);

    // 6) zero masked output rows; out = awT @ o1 (2-term, K = 2*LQ), scatter rows
    zero_masked<<<dim3(S_, B_), 256>>>(out, mask);
    gemm_mma<2><<<dim3(D_ / 128, S_ / 128, B_), 256, SMEM_SZ>>>(
        awts, o1ts, out, nullptr, K2, D_,
        (size_t)S_ * K2, (size_t)D_ * K2, (size_t)S_ * D_, 1.0f,
        scnt, sp, idxb);
}

// round 13
// speedup vs baseline: 1.4585x; 1.1510x over previous
#include <cuda_runtime.h>
#include <cuda_fp16.h>
#include <cstdint>

#define B_  16
#define LQ_ 2048
#define S_  2048
#define D_  1024
#define K2QK 2048    // 2*D  (GEMM1, 2-term)
#define K2   4096    // 2*S == 2*LQ (GEMM2/3 row pitch, 2-term)

// ------------- scratch (__device__ globals = allocation-guard-safe) -------------
static __device__ __half g_qs  [(size_t)B_ * LQ_ * K2QK];  // Q  A-role [h|l] exact
static __device__ __half g_ks  [(size_t)B_ * S_  * K2QK];  // Kc B-role [h|h] dup
static __device__ __half g_vts [(size_t)B_ * D_  * K2];    // Vc^T B-role [h|h] dup
static __device__ __half g_aws [(size_t)B_ * LQ_ * K2];    // awc A-role [h|l]
static __device__ __half g_awts[(size_t)B_ * S_  * K2];    // awc^T A-role [h|l]
static __device__ __half g_o1ts[(size_t)B_ * D_  * K2];    // out1^T B-role [h|h] dup
static __device__ float  g_awc [(size_t)B_ * LQ_ * S_];    // compacted scores/probs
static __device__ int    g_pos [B_ * S_];
static __device__ int    g_idx [B_ * S_];
static __device__ int    g_scnt[B_];
static __device__ int    g_sp  [B_];

// ------------- PTX helpers -------------
__device__ __forceinline__ uint32_t smem_u32(const void* p) {
    uint32_t a;
    asm("{ .reg .u64 t; cvta.to.shared.u64 t, %1; cvt.u32.u64 %0, t; }" : "=r"(a) : "l"(p));
    return a;
}
#define CP_ASYNC16(dst, src) \
    asm volatile("cp.async.cg.shared.global [%0], [%1], 16;" :: "r"(dst), "l"(src) : "memory")
#define CP_COMMIT() asm volatile("cp.async.commit_group;" ::: "memory")
#define CP_WAIT1()  asm volatile("cp.async.wait_group 1;" ::: "memory")
#define CP_WAIT0()  asm volatile("cp.async.wait_group 0;" ::: "memory")

__device__ __forceinline__ void ldsm_x4(uint32_t& r0, uint32_t& r1, uint32_t& r2,
                                        uint32_t& r3, uint32_t addr) {
    asm volatile("ldmatrix.sync.aligned.m8n8.x4.shared.b16 {%0,%1,%2,%3}, [%4];"
                 : "=r"(r0), "=r"(r1), "=r"(r2), "=r"(r3) : "r"(addr));
}
__device__ __forceinline__ void mma_f16(float* c, uint32_t a0, uint32_t a1,
                                        uint32_t a2, uint32_t a3,
                                        uint32_t b0, uint32_t b1) {
    asm volatile(
        "mma.sync.aligned.m16n8k16.row.col.f32.f16.f16.f32 "
        "{%0,%1,%2,%3}, {%4,%5,%6,%7}, {%8,%9}, {%0,%1,%2,%3};"
        : "+f"(c[0]), "+f"(c[1]), "+f"(c[2]), "+f"(c[3])
        : "r"(a0), "r"(a1), "r"(a2), "r"(a3), "r"(b0), "r"(b1));
}
__device__ __forceinline__ void hsplit(float x, __half& h, __half& l) {
    h = __float2half_rn(x);
    l = __float2half_rn(x - __half2float(h));
}

static constexpr int STAGE   = 32768;
static constexpr int SMEM_SZ = 1024 + 3 * STAGE;

// ------------- mma.sync GEMM: C[M,N] = scale * A[M,K] @ B[N,K]^T -------------
// CTA 128x128, 8 warps 64x32, 64-K chunks, SW128 xor swizzle, 3-stage ring.
// MODE 0 (G1): N-compact (exit bn>=SP), K = ld (=2048), fp32 C at ldc.
// MODE 1 (G2): K = 2*SP runtime, pitch ld (=K2); [h|h] dup epi into Tg pitch K2.
// MODE 2 (G3): M-compact (exit bm>=SP), K = ld (=K2); rows scattered via idx.
template<int MODE>
__global__ void __launch_bounds__(256, 2) gemm_mma(
    const __half* __restrict__ Ag,
    const __half* __restrict__ Bg,
    float* __restrict__ Cg, __half* __restrict__ Tg,
    int ld, int ldc, size_t sA, size_t sB, size_t sOut, float scale,
    const int* __restrict__ scnt, const int* __restrict__ sptab,
    const int* __restrict__ idxb)
{
    const int bz = blockIdx.z;
    const int SP = sptab[bz];
    const int bm = blockIdx.y * 128;
    const int bn = blockIdx.x * 128;
    if (MODE == 0 && bn >= SP) return;
    if (MODE == 2 && bm >= SP) return;
    const int K3 = (MODE == 1) ? 2 * SP : ld;

    extern __shared__ char dsm[];
    const uint32_t raw  = smem_u32(dsm);
    const uint32_t base = (raw + 1023u) & ~1023u;
    char* sm = dsm + (base - raw);

    const int tid  = threadIdx.x;
    const int wid  = tid >> 5;
    const int lane = tid & 31;
    const __half* A  = Ag + bz * sA;
    const __half* Bp = Bg + bz * sB;

    const int wm = (wid & 1) * 64;
    const int wn = (wid >> 1) * 32;

    float acc[4][4][4];
    #pragma unroll
    for (int i = 0; i < 4; ++i)
        #pragma unroll
        for (int j = 0; j < 4; ++j)
            #pragma unroll
            for (int r = 0; r < 4; ++r) acc[i][j][r] = 0.f;

    const int lr  = tid >> 1;
    const int lc0 = (tid & 1) << 2;
    const int NT  = K3 >> 6;

    auto load_chunk = [&](int kt) {
        const int kc = kt << 6;
        const uint32_t ab = base + (kt % 3) * STAGE;
        const uint32_t bb = ab + 16384;
        const __half* arow = A  + (size_t)(bm + lr) * ld + kc;
        const __half* brow = Bp + (size_t)(bn + lr) * ld + kc;
        #pragma unroll
        for (int c = 0; c < 4; ++c) {
            int c16 = lc0 + c;
            uint32_t sw = (uint32_t)((c16 ^ (lr & 7)) << 4);
            CP_ASYNC16(ab + (uint32_t)(lr << 7) + sw, arow + (c16 << 3));
            CP_ASYNC16(bb + (uint32_t)(lr << 7) + sw, brow + (c16 << 3));
        }
        CP_COMMIT();
    };

    load_chunk(0);
    load_chunk(1);

    for (int kt = 0; kt < NT; ++kt) {
        if (kt + 1 < NT) CP_WAIT1();
        else             CP_WAIT0();
        __syncthreads();
        if (kt + 2 < NT) load_chunk(kt + 2);

        const uint32_t ab = base + (kt % 3) * STAGE;
        const uint32_t bb = ab + 16384;
        const int t4 = lane >> 3;

        #pragma unroll
        for (int ks = 0; ks < 4; ++ks) {
            uint32_t Af[4][4];
            #pragma unroll
            for (int mt = 0; mt < 4; ++mt) {
                int row = wm + mt * 16 + ((t4 & 1) << 3) + (lane & 7);
                int c16 = ks * 2 + (t4 >> 1);
                uint32_t addr = ab + (uint32_t)(row << 7)
                              + (uint32_t)((c16 ^ (row & 7)) << 4);
                ldsm_x4(Af[mt][0], Af[mt][1], Af[mt][2], Af[mt][3], addr);
            }
            uint32_t Bf[2][4];
            #pragma unroll
            for (int gt = 0; gt < 2; ++gt) {
                int row = wn + gt * 16 + ((t4 >> 1) << 3) + (lane & 7);
                int c16 = ks * 2 + (t4 & 1);
                uint32_t addr = bb + (uint32_t)(row << 7)
                              + (uint32_t)((c16 ^ (row & 7)) << 4);
                ldsm_x4(Bf[gt][0], Bf[gt][1], Bf[gt][2], Bf[gt][3], addr);
            }
            #pragma unroll
            for (int mt = 0; mt < 4; ++mt)
                #pragma unroll
                for (int ng = 0; ng < 4; ++ng) {
                    const uint32_t* bg = Bf[ng >> 1];
                    mma_f16(acc[mt][ng],
                            Af[mt][0], Af[mt][1], Af[mt][2], Af[mt][3],
                            bg[(ng & 1) * 2], bg[(ng & 1) * 2 + 1]);
                }
        }
    }
    __syncthreads();

    const int qr = lane >> 2;
    const int qc = (lane & 3) << 1;

    if (MODE == 0 || MODE == 2) {
        float* slab = reinterpret_cast<float*>(sm);   // [m][n] pitch 132
        #pragma unroll
        for (int mt = 0; mt < 4; ++mt)
            #pragma unroll
            for (int ng = 0; ng < 4; ++ng) {
                int m = wm + mt * 16 + qr;
                int n = wn + ng * 8 + qc;
                float* p0 = slab + (size_t)m * 132 + n;
                p0[0] = acc[mt][ng][0] * scale;
                p0[1] = acc[mt][ng][1] * scale;
                float* p1 = p0 + 8 * 132;
                p1[0] = acc[mt][ng][2] * scale;
                p1[1] = acc[mt][ng][3] * scale;
            }
        __syncthreads();
        float* Cb = Cg + bz * sOut;
        const int Sc = (MODE == 2) ? scnt[bz] : 0;
        #pragma unroll
        for (int it = 0; it < 16; ++it) {
            int idx = tid + (it << 8);
            int r = idx >> 5, c = (idx & 31) << 2;
            float4 v = *reinterpret_cast<float4*>(slab + (size_t)r * 132 + c);
            if (MODE == 0) {
                *reinterpret_cast<float4*>(Cb + (size_t)(bm + r) * ldc + bn + c) = v;
            } else {
                int gr = bm + r;
                if (gr < Sc) {
                    int trow = idxb[bz * S_ + gr];
                    *reinterpret_cast<float4*>(Cb + (size_t)trow * ldc + bn + c) = v;
                }
            }
        }
    } else {
        float* slab = reinterpret_cast<float*>(sm);   // [n][m] pitch 132
        #pragma unroll
        for (int mt = 0; mt < 4; ++mt)
            #pragma unroll
            for (int ng = 0; ng < 4; ++ng) {
                int m = wm + mt * 16 + qr;
                int n = wn + ng * 8 + qc;
                slab[(size_t)n * 132 + m]           = acc[mt][ng][0];
                slab[(size_t)(n + 1) * 132 + m]     = acc[mt][ng][1];
                slab[(size_t)n * 132 + m + 8]       = acc[mt][ng][2];
                slab[(size_t)(n + 1) * 132 + m + 8] = acc[mt][ng][3];
            }
        __syncthreads();
        __half* T = Tg + bz * sOut;
        #pragma unroll
        for (int it = 0; it < 16; ++it) {
            int idx = tid + (it << 8);
            int n = idx >> 5, mc = (idx & 31) << 2;
            float4 v = *reinterpret_cast<float4*>(slab + (size_t)n * 132 + mc);
            float xs[4] = {v.x, v.y, v.z, v.w};
            __align__(8) __half h[4];
            #pragma unroll
            for (int i = 0; i < 4; ++i) h[i] = __float2half_rn(xs[i]);
            __half* dst = T + (size_t)(bn + n) * K2 + bm + mc;
            *reinterpret_cast<uint2*>(dst)       = *reinterpret_cast<uint2*>(h);
            *reinterpret_cast<uint2*>(dst + LQ_) = *reinterpret_cast<uint2*>(h);
        }
    }
}

// ------------- mask prefix scan -------------
__global__ void __launch_bounds__(256) scan_mask(
    const int* __restrict__ mask, int* __restrict__ pos, int* __restrict__ idxb,
    int* __restrict__ scnt, int* __restrict__ sptab)
{
    const int b = blockIdx.x;
    const int* mp = mask + b * S_;
    const int t = threadIdx.x;
    __shared__ int part[256];
    int loc[8], sum = 0;
    #pragma unroll
    for (int i = 0; i < 8; ++i) { loc[i] = mp[t * 8 + i]; sum += loc[i]; }
    part[t] = sum;
    __syncthreads();
    for (int off = 1; off < 256; off <<= 1) {
        int v = (t >= off) ? part[t - off] : 0;
        __syncthreads();
        part[t] += v;
        __syncthreads();
    }
    int run = part[t] - sum;
    #pragma unroll
    for (int i = 0; i < 8; ++i) {
        int s = t * 8 + i;
        pos[b * S_ + s] = run;
        if (loc[i]) { idxb[b * S_ + run] = s; ++run; }
    }
    if (t == 255) {
        scnt[b]  = run;
        sptab[b] = (run + 127) & ~127;
    }
}

// ------------- Q split A-role [h|l] exact, pitch 2048 -------------
__global__ void __launch_bounds__(256) split_rows_q(
    const float* __restrict__ in, __half* __restrict__ out)
{
    size_t idx = (size_t)blockIdx.x * 256 + threadIdx.x;
    size_t row = idx >> 8;
    int    c   = (int)(idx & 255) << 2;
    float4 v = *reinterpret_cast<const float4*>(in + row * D_ + c);
    float xs[4] = {v.x, v.y, v.z, v.w};
    __align__(8) __half h[4], l[4];
    #pragma unroll
    for (int i = 0; i < 4; ++i) hsplit(xs[i], h[i], l[i]);
    __half* o = out + row * (size_t)K2QK + c;
    *reinterpret_cast<uint2*>(o)      = *reinterpret_cast<uint2*>(h);
    *reinterpret_cast<uint2*>(o + D_) = *reinterpret_cast<uint2*>(l);
}

// ------------- K gather B-role [h|h] dup, pitch 2048 -------------
__global__ void __launch_bounds__(256) gather_split_k(
    const float* __restrict__ k, __half* __restrict__ out,
    const int* __restrict__ idxb, const int* __restrict__ scnt,
    const int* __restrict__ sptab)
{
    const int b = blockIdx.y, j = blockIdx.x;
    if (j >= sptab[b]) return;
    const int t = threadIdx.x, c = t << 2;
    __half* o = out + ((size_t)b * S_ + j) * K2QK + c;
    __align__(8) __half h[4];
    if (j < scnt[b]) {
        const float* src = k + ((size_t)b * S_ + idxb[b * S_ + j]) * D_ + c;
        float4 v = *reinterpret_cast<const float4*>(src);
        float xs[4] = {v.x, v.y, v.z, v.w};
        #pragma unroll
        for (int i = 0; i < 4; ++i) h[i] = __float2half_rn(xs[i]);
    } else {
        #pragma unroll
        for (int i = 0; i < 4; ++i) h[i] = __float2half_rn(0.f);
    }
    *reinterpret_cast<uint2*>(o)      = *reinterpret_cast<uint2*>(h);
    *reinterpret_cast<uint2*>(o + D_) = *reinterpret_cast<uint2*>(h);
}

// ------------- V gather + transpose B-role [h|h] dup, seg pitch SP -------------
__global__ void __launch_bounds__(256) gather_tsplit_v(
    const float* __restrict__ v, __half* __restrict__ out,
    const int* __restrict__ idxb, const int* __restrict__ scnt,
    const int* __restrict__ sptab)
{
    const int b  = blockIdx.z;
    const int SP = sptab[b], Sc = scnt[b];
    const int j0 = blockIdx.x * 32;
    if (j0 >= SP) return;
    const int d0 = blockIdx.y * 32;
    const float* ip = v + (size_t)b * S_ * D_;
    __half* op = out + (size_t)b * D_ * K2;
    __shared__ float tile[32][33];
    const int tx = threadIdx.x & 31, ty = threadIdx.x >> 5;
    #pragma unroll
    for (int i = 0; i < 4; ++i) {
        int jr = j0 + ty + i * 8;
        float val = 0.f;
        if (jr < Sc) val = ip[(size_t)idxb[b * S_ + jr] * D_ + d0 + tx];
        tile[ty + i * 8][tx] = val;
    }
    __syncthreads();
    #pragma unroll
    for (int i = 0; i < 4; ++i) {
        int cc = ty + i * 8;
        __half h = __float2half_rn(tile[tx][cc]);
        __half* o = op + (size_t)(d0 + cc) * K2 + j0 + tx;
        o[0]  = h;
        o[SP] = h;
    }
}

// ------------- softmax compact + full-aw scatter + A-role [h|l] split -------------
__global__ void __launch_bounds__(256) softmax_compact(
    float* __restrict__ awc, float* __restrict__ aw, const int* __restrict__ mask,
    __half* __restrict__ aws, const int* __restrict__ pos,
    const int* __restrict__ scnt, const int* __restrict__ sptab)
{
    const int row = blockIdx.x;
    const int b   = row >> 11;
    const int Sc  = scnt[b], SP = sptab[b];
    float*      cp = awc + (size_t)row * S_;
    float*      rp = aw  + (size_t)row * S_;
    __half*     ap = aws + (size_t)row * K2;
    const int*  mp = mask + b * S_;
    const int*  pp = pos  + b * S_;
    const int t = threadIdx.x;
    const float NEG_INF = __int_as_float(0xff800000);

    __shared__ float parr[2048];
    __shared__ float smax[8], ssum[8];

    float vv[8];
    float mx = NEG_INF;
    #pragma unroll
    for (int i = 0; i < 8; ++i) {
        int j = t + (i << 8);
        vv[i] = (j < Sc) ? cp[j] : NEG_INF;
        mx = fmaxf(mx, vv[i]);
    }
    #pragma unroll
    for (int off = 16; off > 0; off >>= 1)
        mx = fmaxf(mx, __shfl_xor_sync(0xffffffffu, mx, off));
    if ((t & 31) == 0) smax[t >> 5] = mx;
    __syncthreads();
    float rmax = smax[0];
    #pragma unroll
    for (int i = 1; i < 8; ++i) rmax = fmaxf(rmax, smax[i]);

    float e[8], sum = 0.f;
    #pragma unroll
    for (int i = 0; i < 8; ++i) {
        int j = t + (i << 8);
        e[i] = (j < Sc) ? __expf(vv[i] - rmax) : 0.f;
        sum += e[i];
    }
    #pragma unroll
    for (int off = 16; off > 0; off >>= 1)
        sum += __shfl_xor_sync(0xffffffffu, sum, off);
    if ((t & 31) == 0) ssum[t >> 5] = sum;
    __syncthreads();
    float rsum = 0.f;
    #pragma unroll
    for (int i = 0; i < 8; ++i) rsum += ssum[i];
    const float inv = 1.f / rsum;

    #pragma unroll
    for (int i = 0; i < 8; ++i) {
        int j = t + (i << 8);
        if (j < SP) {
            float p = e[i] * inv;
            cp[j]   = p;
            parr[j] = p;
            __half h, l;
            hsplit(p, h, l);
            ap[j]      = h;
            ap[SP + j] = l;
        }
    }
    __syncthreads();
    #pragma unroll
    for (int i = 0; i < 8; ++i) {
        int s = t + (i << 8);
        rp[s] = mp[s] ? parr[pp[s]] : 0.f;
    }
}

// ------------- transpose+split awc -> awts A-role [h|l], pitch K2 -------------
__global__ void __launch_bounds__(256) tsplit_awc(
    const float* __restrict__ awc, __half* __restrict__ out,
    const int* __restrict__ sptab)
{
    const int b  = blockIdx.z;
    const int c0 = blockIdx.y * 32;
    if (c0 >= sptab[b]) return;
    const int r0 = blockIdx.x * 32;
    const float* ip = awc + (size_t)b * LQ_ * S_;
    __half* op = out + (size_t)b * S_ * K2;
    __shared__ float tile[32][33];
    const int tx = threadIdx.x & 31, ty = threadIdx.x >> 5;
    #pragma unroll
    for (int i = 0; i < 4; ++i)
        tile[ty + i * 8][tx] = ip[(size_t)(r0 + ty + i * 8) * S_ + c0 + tx];
    __syncthreads();
    #pragma unroll
    for (int i = 0; i < 4; ++i) {
        int cc = ty + i * 8;
        __half h, l;
        hsplit(tile[tx][cc], h, l);
        __half* o = op + (size_t)(c0 + cc) * K2 + r0 + tx;
        o[0]   = h;
        o[LQ_] = l;
    }
}

// ------------- zero output rows where mask == 0 -------------
__global__ void __launch_bounds__(256) zero_masked(
    float* __restrict__ out, const int* __restrict__ mask)
{
    const int b = blockIdx.y, s = blockIdx.x;
    if (mask[b * S_ + s]) return;
    float* r = out + ((size_t)b * S_ + s) * D_;
    float4 z = make_float4(0.f, 0.f, 0.f, 0.f);
    *reinterpret_cast<float4*>(r + (threadIdx.x << 2)) = z;
}

extern "C" void kernel_launch(void* const* d_in, const int* in_sizes, int n_in,
                              void* d_out, int out_size)
{
    const float* q    = (const float*)d_in[0];
    const float* kk   = (const float*)d_in[1];
    const float* v    = (const float*)d_in[2];
    const int*   mask = (const int*)  d_in[3];

    float* out = (float*)d_out;                       // output [B,S,D]
    float* aw  = out + (size_t)B_ * S_ * D_;          // attention_weights [B,LQ,S]

    void* p;
    cudaGetSymbolAddress(&p, g_qs);   __half* qs   = (__half*)p;
    cudaGetSymbolAddress(&p, g_ks);   __half* ks   = (__half*)p;
    cudaGetSymbolAddress(&p, g_vts);  __half* vts  = (__half*)p;
    cudaGetSymbolAddress(&p, g_aws);  __half* aws  = (__half*)p;
    cudaGetSymbolAddress(&p, g_awts); __half* awts = (__half*)p;
    cudaGetSymbolAddress(&p, g_o1ts); __half* o1ts = (__half*)p;
    cudaGetSymbolAddress(&p, g_awc);  float* awc  = (float*)p;
    cudaGetSymbolAddress(&p, g_pos);  int*   pos  = (int*)p;
    cudaGetSymbolAddress(&p, g_idx);  int*   idxb = (int*)p;
    cudaGetSymbolAddress(&p, g_scnt); int*   scnt = (int*)p;
    cudaGetSymbolAddress(&p, g_sp);   int*   sp   = (int*)p;

    cudaFuncSetAttribute(gemm_mma<0>, cudaFuncAttributeMaxDynamicSharedMemorySize, SMEM_SZ);
    cudaFuncSetAttribute(gemm_mma<1>, cudaFuncAttributeMaxDynamicSharedMemorySize, SMEM_SZ);
    cudaFuncSetAttribute(gemm_mma<2>, cudaFuncAttributeMaxDynamicSharedMemorySize, SMEM_SZ);

    // 0) mask scan
    scan_mask<<<B_, 256>>>(mask, pos, idxb, scnt, sp);

    // 1) operand prep
    split_rows_q<<<(int)(((size_t)B_ * LQ_ * D_ / 4) / 256), 256>>>(q, qs);
    gather_split_k<<<dim3(S_, B_), 256>>>(kk, ks, idxb, scnt, sp);
    gather_tsplit_v<<<dim3(S_ / 32, D_ / 32, B_), 256>>>(v, vts, idxb, scnt, sp);

    // 2) scores_c = Q @ Kc^T / 32 -> awc  (2-term fp16, N-compact, K=2048)
    gemm_mma<0><<<dim3(S_ / 128, LQ_ / 128, B_), 256, SMEM_SZ>>>(
        qs, ks, awc, nullptr, K2QK, S_,
        (size_t)LQ_ * K2QK, (size_t)S_ * K2QK, (size_t)LQ_ * S_, 0.03125f,
        scnt, sp, idxb);

    // 3) softmax on compacted rows; scatter full aw; A-role [h|l] split
    softmax_compact<<<B_ * LQ_, 256>>>(awc, aw, mask, aws, pos, scnt, sp);

    // 4) awc^T split (A-role [h|l], compacted rows)
    tsplit_awc<<<dim3(LQ_ / 32, S_ / 32, B_), 256>>>(awc, awts, sp);

    // 5) out1 = awc @ Vc  (2-term, K = 2*SP) -> o1ts ([h|h] dup epi)
    gemm_mma<1><<<dim3(D_ / 128, LQ_ / 128, B_), 256, SMEM_SZ>>>(
        aws, vts, nullptr, o1ts, K2, 0,
        (size_t)LQ_ * K2, (size_t)D_ * K2, (size_t)D_ * K2, 1.0f,
        scnt, sp, idxb);

    // 6) zero masked output rows; out = awT @ o1 (2-term, K = 2*LQ), scatter rows
    zero_masked<<<dim3(S_, B_), 256>>>(out, mask);
    gemm_mma<2><<<dim3(D_ / 128, S_ / 128, B_), 256, SMEM_SZ>>>(
        awts, o1ts, out, nullptr, K2, D_,
        (size_t)S_ * K2, (size_t)D_ * K2, (size_t)S_ * D_, 1.0f,
        scnt, sp, idxb);
}

// round 14
// speedup vs baseline: 2.0167x; 1.3827x over previous
#include <cuda_runtime.h>
#include <cuda_fp16.h>
#include <cstdint>

#define B_  16
#define LQ_ 2048
#define S_  2048
#define D_  1024
#define K2QK 2048    // 2*D (GEMM1, 2-term: Q exact [h|l], K dup [h|h])
#define KA   2048    // GEMM2/3 row pitch (single-term fp16)

// ------------- scratch (__device__ globals = allocation-guard-safe) -------------
static __device__ __half g_qs  [(size_t)B_ * LQ_ * K2QK];  // Q  A-role [h|l] exact
static __device__ __half g_ks  [(size_t)B_ * S_  * K2QK];  // Kc B-role [h|h] dup
static __device__ __half g_vts [(size_t)B_ * D_  * KA];    // Vc^T fp16 single
static __device__ __half g_aws [(size_t)B_ * LQ_ * KA];    // awc fp16 single
static __device__ __half g_awts[(size_t)B_ * S_  * KA];    // awc^T fp16 single
static __device__ __half g_o1ts[(size_t)B_ * D_  * KA];    // out1^T fp16 single
static __device__ float  g_awc [(size_t)B_ * LQ_ * S_];    // compacted scores/probs
static __device__ int    g_pos [B_ * S_];
static __device__ int    g_idx [B_ * S_];
static __device__ int    g_scnt[B_];
static __device__ int    g_sp  [B_];

// ------------- PTX helpers -------------
__device__ __forceinline__ uint32_t smem_u32(const void* p) {
    uint32_t a;
    asm("{ .reg .u64 t; cvta.to.shared.u64 t, %1; cvt.u32.u64 %0, t; }" : "=r"(a) : "l"(p));
    return a;
}
#define CP_ASYNC16(dst, src) \
    asm volatile("cp.async.cg.shared.global [%0], [%1], 16;" :: "r"(dst), "l"(src) : "memory")
#define CP_COMMIT() asm volatile("cp.async.commit_group;" ::: "memory")
#define CP_WAIT1()  asm volatile("cp.async.wait_group 1;" ::: "memory")
#define CP_WAIT0()  asm volatile("cp.async.wait_group 0;" ::: "memory")

__device__ __forceinline__ void ldsm_x4(uint32_t& r0, uint32_t& r1, uint32_t& r2,
                                        uint32_t& r3, uint32_t addr) {
    asm volatile("ldmatrix.sync.aligned.m8n8.x4.shared.b16 {%0,%1,%2,%3}, [%4];"
                 : "=r"(r0), "=r"(r1), "=r"(r2), "=r"(r3) : "r"(addr));
}
__device__ __forceinline__ void mma_f16(float* c, uint32_t a0, uint32_t a1,
                                        uint32_t a2, uint32_t a3,
                                        uint32_t b0, uint32_t b1) {
    asm volatile(
        "mma.sync.aligned.m16n8k16.row.col.f32.f16.f16.f32 "
        "{%0,%1,%2,%3}, {%4,%5,%6,%7}, {%8,%9}, {%0,%1,%2,%3};"
        : "+f"(c[0]), "+f"(c[1]), "+f"(c[2]), "+f"(c[3])
        : "r"(a0), "r"(a1), "r"(a2), "r"(a3), "r"(b0), "r"(b1));
}
__device__ __forceinline__ void hsplit(float x, __half& h, __half& l) {
    h = __float2half_rn(x);
    l = __float2half_rn(x - __half2float(h));
}

static constexpr int STAGE   = 32768;
static constexpr int SMEM_SZ = 1024 + 3 * STAGE;

// ------------- mma.sync GEMM: C[M,N] = scale * A[M,K] @ B[N,K]^T -------------
// CTA 128x128, 8 warps 64x32, 64-K chunks, SW128 xor swizzle, 3-stage ring.
// MODE 0 (G1): N-compact (exit bn>=SP), K = ld (=2048), fp32 C at ldc.
// MODE 1 (G2): K = SP runtime, pitch ld (=KA); fp16 transposed epi into Tg pitch KA.
// MODE 2 (G3): M-compact (exit bm>=SP), K = ld (=KA); rows scattered via idx.
template<int MODE>
__global__ void __launch_bounds__(256, 2) gemm_mma(
    const __half* __restrict__ Ag,
    const __half* __restrict__ Bg,
    float* __restrict__ Cg, __half* __restrict__ Tg,
    int ld, int ldc, size_t sA, size_t sB, size_t sOut, float scale,
    const int* __restrict__ scnt, const int* __restrict__ sptab,
    const int* __restrict__ idxb)
{
    const int bz = blockIdx.z;
    const int SP = sptab[bz];
    const int bm = blockIdx.y * 128;
    const int bn = blockIdx.x * 128;
    if (MODE == 0 && bn >= SP) return;
    if (MODE == 2 && bm >= SP) return;
    const int K3 = (MODE == 1) ? SP : ld;

    extern __shared__ char dsm[];
    const uint32_t raw  = smem_u32(dsm);
    const uint32_t base = (raw + 1023u) & ~1023u;
    char* sm = dsm + (base - raw);

    const int tid  = threadIdx.x;
    const int wid  = tid >> 5;
    const int lane = tid & 31;
    const __half* A  = Ag + bz * sA;
    const __half* Bp = Bg + bz * sB;

    const int wm = (wid & 1) * 64;
    const int wn = (wid >> 1) * 32;

    float acc[4][4][4];
    #pragma unroll
    for (int i = 0; i < 4; ++i)
        #pragma unroll
        for (int j = 0; j < 4; ++j)
            #pragma unroll
            for (int r = 0; r < 4; ++r) acc[i][j][r] = 0.f;

    const int lr  = tid >> 1;
    const int lc0 = (tid & 1) << 2;
    const int NT  = K3 >> 6;

    auto load_chunk = [&](int kt) {
        const int kc = kt << 6;
        const uint32_t ab = base + (kt % 3) * STAGE;
        const uint32_t bb = ab + 16384;
        const __half* arow = A  + (size_t)(bm + lr) * ld + kc;
        const __half* brow = Bp + (size_t)(bn + lr) * ld + kc;
        #pragma unroll
        for (int c = 0; c < 4; ++c) {
            int c16 = lc0 + c;
            uint32_t sw = (uint32_t)((c16 ^ (lr & 7)) << 4);
            CP_ASYNC16(ab + (uint32_t)(lr << 7) + sw, arow + (c16 << 3));
            CP_ASYNC16(bb + (uint32_t)(lr << 7) + sw, brow + (c16 << 3));
        }
        CP_COMMIT();
    };

    load_chunk(0);
    load_chunk(1);

    for (int kt = 0; kt < NT; ++kt) {
        if (kt + 1 < NT) CP_WAIT1();
        else             CP_WAIT0();
        __syncthreads();
        if (kt + 2 < NT) load_chunk(kt + 2);

        const uint32_t ab = base + (kt % 3) * STAGE;
        const uint32_t bb = ab + 16384;
        const int t4 = lane >> 3;

        #pragma unroll
        for (int ks = 0; ks < 4; ++ks) {
            uint32_t Af[4][4];
            #pragma unroll
            for (int mt = 0; mt < 4; ++mt) {
                int row = wm + mt * 16 + ((t4 & 1) << 3) + (lane & 7);
                int c16 = ks * 2 + (t4 >> 1);
                uint32_t addr = ab + (uint32_t)(row << 7)
                              + (uint32_t)((c16 ^ (row & 7)) << 4);
                ldsm_x4(Af[mt][0], Af[mt][1], Af[mt][2], Af[mt][3], addr);
            }
            uint32_t Bf[2][4];
            #pragma unroll
            for (int gt = 0; gt < 2; ++gt) {
                int row = wn + gt * 16 + ((t4 >> 1) << 3) + (lane & 7);
                int c16 = ks * 2 + (t4 & 1);
                uint32_t addr = bb + (uint32_t)(row << 7)
                              + (uint32_t)((c16 ^ (row & 7)) << 4);
                ldsm_x4(Bf[gt][0], Bf[gt][1], Bf[gt][2], Bf[gt][3], addr);
            }
            #pragma unroll
            for (int mt = 0; mt < 4; ++mt)
                #pragma unroll
                for (int ng = 0; ng < 4; ++ng) {
                    const uint32_t* bg = Bf[ng >> 1];
                    mma_f16(acc[mt][ng],
                            Af[mt][0], Af[mt][1], Af[mt][2], Af[mt][3],
                            bg[(ng & 1) * 2], bg[(ng & 1) * 2 + 1]);
                }
        }
    }
    __syncthreads();

    const int qr = lane >> 2;
    const int qc = (lane & 3) << 1;

    if (MODE == 0 || MODE == 2) {
        float* slab = reinterpret_cast<float*>(sm);   // [m][n] pitch 132
        #pragma unroll
        for (int mt = 0; mt < 4; ++mt)
            #pragma unroll
            for (int ng = 0; ng < 4; ++ng) {
                int m = wm + mt * 16 + qr;
                int n = wn + ng * 8 + qc;
                float* p0 = slab + (size_t)m * 132 + n;
                p0[0] = acc[mt][ng][0] * scale;
                p0[1] = acc[mt][ng][1] * scale;
                float* p1 = p0 + 8 * 132;
                p1[0] = acc[mt][ng][2] * scale;
                p1[1] = acc[mt][ng][3] * scale;
            }
        __syncthreads();
        float* Cb = Cg + bz * sOut;
        const int Sc = (MODE == 2) ? scnt[bz] : 0;
        #pragma unroll
        for (int it = 0; it < 16; ++it) {
            int idx = tid + (it << 8);
            int r = idx >> 5, c = (idx & 31) << 2;
            float4 v = *reinterpret_cast<float4*>(slab + (size_t)r * 132 + c);
            if (MODE == 0) {
                *reinterpret_cast<float4*>(Cb + (size_t)(bm + r) * ldc + bn + c) = v;
            } else {
                int gr = bm + r;
                if (gr < Sc) {
                    int trow = idxb[bz * S_ + gr];
                    *reinterpret_cast<float4*>(Cb + (size_t)trow * ldc + bn + c) = v;
                }
            }
        }
    } else {
        float* slab = reinterpret_cast<float*>(sm);   // [n][m] pitch 132
        #pragma unroll
        for (int mt = 0; mt < 4; ++mt)
            #pragma unroll
            for (int ng = 0; ng < 4; ++ng) {
                int m = wm + mt * 16 + qr;
                int n = wn + ng * 8 + qc;
                slab[(size_t)n * 132 + m]           = acc[mt][ng][0];
                slab[(size_t)(n + 1) * 132 + m]     = acc[mt][ng][1];
                slab[(size_t)n * 132 + m + 8]       = acc[mt][ng][2];
                slab[(size_t)(n + 1) * 132 + m + 8] = acc[mt][ng][3];
            }
        __syncthreads();
        __half* T = Tg + bz * sOut;
        #pragma unroll
        for (int it = 0; it < 16; ++it) {
            int idx = tid + (it << 8);
            int n = idx >> 5, mc = (idx & 31) << 2;
            float4 v = *reinterpret_cast<float4*>(slab + (size_t)n * 132 + mc);
            float xs[4] = {v.x, v.y, v.z, v.w};
            __align__(8) __half h[4];
            #pragma unroll
            for (int i = 0; i < 4; ++i) h[i] = __float2half_rn(xs[i]);
            __half* dst = T + (size_t)(bn + n) * KA + bm + mc;
            *reinterpret_cast<uint2*>(dst) = *reinterpret_cast<uint2*>(h);
        }
    }
}

// ------------- mask prefix scan -------------
__global__ void __launch_bounds__(256) scan_mask(
    const int* __restrict__ mask, int* __restrict__ pos, int* __restrict__ idxb,
    int* __restrict__ scnt, int* __restrict__ sptab)
{
    const int b = blockIdx.x;
    const int* mp = mask + b * S_;
    const int t = threadIdx.x;
    __shared__ int part[256];
    int loc[8], sum = 0;
    #pragma unroll
    for (int i = 0; i < 8; ++i) { loc[i] = mp[t * 8 + i]; sum += loc[i]; }
    part[t] = sum;
    __syncthreads();
    for (int off = 1; off < 256; off <<= 1) {
        int v = (t >= off) ? part[t - off] : 0;
        __syncthreads();
        part[t] += v;
        __syncthreads();
    }
    int run = part[t] - sum;
    #pragma unroll
    for (int i = 0; i < 8; ++i) {
        int s = t * 8 + i;
        pos[b * S_ + s] = run;
        if (loc[i]) { idxb[b * S_ + run] = s; ++run; }
    }
    if (t == 255) {
        scnt[b]  = run;
        sptab[b] = (run + 127) & ~127;
    }
}

// ------------- Q split A-role [h|l] exact, pitch 2048 -------------
__global__ void __launch_bounds__(256) split_rows_q(
    const float* __restrict__ in, __half* __restrict__ out)
{
    size_t idx = (size_t)blockIdx.x * 256 + threadIdx.x;
    size_t row = idx >> 8;
    int    c   = (int)(idx & 255) << 2;
    float4 v = *reinterpret_cast<const float4*>(in + row * D_ + c);
    float xs[4] = {v.x, v.y, v.z, v.w};
    __align__(8) __half h[4], l[4];
    #pragma unroll
    for (int i = 0; i < 4; ++i) hsplit(xs[i], h[i], l[i]);
    __half* o = out + row * (size_t)K2QK + c;
    *reinterpret_cast<uint2*>(o)      = *reinterpret_cast<uint2*>(h);
    *reinterpret_cast<uint2*>(o + D_) = *reinterpret_cast<uint2*>(l);
}

// ------------- K gather B-role [h|h] dup, pitch 2048 -------------
__global__ void __launch_bounds__(256) gather_split_k(
    const float* __restrict__ k, __half* __restrict__ out,
    const int* __restrict__ idxb, const int* __restrict__ scnt,
    const int* __restrict__ sptab)
{
    const int b = blockIdx.y, j = blockIdx.x;
    if (j >= sptab[b]) return;
    const int t = threadIdx.x, c = t << 2;
    __half* o = out + ((size_t)b * S_ + j) * K2QK + c;
    __align__(8) __half h[4];
    if (j < scnt[b]) {
        const float* src = k + ((size_t)b * S_ + idxb[b * S_ + j]) * D_ + c;
        float4 v = *reinterpret_cast<const float4*>(src);
        float xs[4] = {v.x, v.y, v.z, v.w};
        #pragma unroll
        for (int i = 0; i < 4; ++i) h[i] = __float2half_rn(xs[i]);
    } else {
        #pragma unroll
        for (int i = 0; i < 4; ++i) h[i] = __float2half_rn(0.f);
    }
    *reinterpret_cast<uint2*>(o)      = *reinterpret_cast<uint2*>(h);
    *reinterpret_cast<uint2*>(o + D_) = *reinterpret_cast<uint2*>(h);
}

// ------------- V gather + transpose, fp16 single, pitch KA -------------
__global__ void __launch_bounds__(256) gather_tsplit_v(
    const float* __restrict__ v, __half* __restrict__ out,
    const int* __restrict__ idxb, const int* __restrict__ scnt,
    const int* __restrict__ sptab)
{
    const int b  = blockIdx.z;
    const int SP = sptab[b], Sc = scnt[b];
    const int j0 = blockIdx.x * 32;
    if (j0 >= SP) return;
    const int d0 = blockIdx.y * 32;
    const float* ip = v + (size_t)b * S_ * D_;
    __half* op = out + (size_t)b * D_ * KA;
    __shared__ float tile[32][33];
    const int tx = threadIdx.x & 31, ty = threadIdx.x >> 5;
    #pragma unroll
    for (int i = 0; i < 4; ++i) {
        int jr = j0 + ty + i * 8;
        float val = 0.f;
        if (jr < Sc) val = ip[(size_t)idxb[b * S_ + jr] * D_ + d0 + tx];
        tile[ty + i * 8][tx] = val;
    }
    __syncthreads();
    #pragma unroll
    for (int i = 0; i < 4; ++i) {
        int cc = ty + i * 8;
        op[(size_t)(d0 + cc) * KA + j0 + tx] = __float2half_rn(tile[tx][cc]);
    }
}

// ------------- softmax compact + full-aw scatter + fp16 single write -------------
__global__ void __launch_bounds__(256) softmax_compact(
    float* __restrict__ awc, float* __restrict__ aw, const int* __restrict__ mask,
    __half* __restrict__ aws, const int* __restrict__ pos,
    const int* __restrict__ scnt, const int* __restrict__ sptab)
{
    const int row = blockIdx.x;
    const int b   = row >> 11;
    const int Sc  = scnt[b], SP = sptab[b];
    float*      cp = awc + (size_t)row * S_;
    float*      rp = aw  + (size_t)row * S_;
    __half*     ap = aws + (size_t)row * KA;
    const int*  mp = mask + b * S_;
    const int*  pp = pos  + b * S_;
    const int t = threadIdx.x;
    const float NEG_INF = __int_as_float(0xff800000);

    __shared__ float parr[2048];
    __shared__ float smax[8], ssum[8];

    float vv[8];
    float mx = NEG_INF;
    #pragma unroll
    for (int i = 0; i < 8; ++i) {
        int j = t + (i << 8);
        vv[i] = (j < Sc) ? cp[j] : NEG_INF;
        mx = fmaxf(mx, vv[i]);
    }
    #pragma unroll
    for (int off = 16; off > 0; off >>= 1)
        mx = fmaxf(mx, __shfl_xor_sync(0xffffffffu, mx, off));
    if ((t & 31) == 0) smax[t >> 5] = mx;
    __syncthreads();
    float rmax = smax[0];
    #pragma unroll
    for (int i = 1; i < 8; ++i) rmax = fmaxf(rmax, smax[i]);

    float e[8], sum = 0.f;
    #pragma unroll
    for (int i = 0; i < 8; ++i) {
        int j = t + (i << 8);
        e[i] = (j < Sc) ? __expf(vv[i] - rmax) : 0.f;
        sum += e[i];
    }
    #pragma unroll
    for (int off = 16; off > 0; off >>= 1)
        sum += __shfl_xor_sync(0xffffffffu, sum, off);
    if ((t & 31) == 0) ssum[t >> 5] = sum;
    __syncthreads();
    float rsum = 0.f;
    #pragma unroll
    for (int i = 0; i < 8; ++i) rsum += ssum[i];
    const float inv = 1.f / rsum;

    #pragma unroll
    for (int i = 0; i < 8; ++i) {
        int j = t + (i << 8);
        if (j < SP) {
            float p = e[i] * inv;
            cp[j]   = p;
            parr[j] = p;
            ap[j]   = __float2half_rn(p);
        }
    }
    __syncthreads();
    #pragma unroll
    for (int i = 0; i < 8; ++i) {
        int s = t + (i << 8);
        rp[s] = mp[s] ? parr[pp[s]] : 0.f;
    }
}

// ------------- transpose awc -> awts fp16 single, pitch KA -------------
__global__ void __launch_bounds__(256) tsplit_awc(
    const float* __restrict__ awc, __half* __restrict__ out,
    const int* __restrict__ sptab)
{
    const int b  = blockIdx.z;
    const int c0 = blockIdx.y * 32;
    if (c0 >= sptab[b]) return;
    const int r0 = blockIdx.x * 32;
    const float* ip = awc + (size_t)b * LQ_ * S_;
    __half* op = out + (size_t)b * S_ * KA;
    __shared__ float tile[32][33];
    const int tx = threadIdx.x & 31, ty = threadIdx.x >> 5;
    #pragma unroll
    for (int i = 0; i < 4; ++i)
        tile[ty + i * 8][tx] = ip[(size_t)(r0 + ty + i * 8) * S_ + c0 + tx];
    __syncthreads();
    #pragma unroll
    for (int i = 0; i < 4; ++i) {
        int cc = ty + i * 8;
        op[(size_t)(c0 + cc) * KA + r0 + tx] = __float2half_rn(tile[tx][cc]);
    }
}

// ------------- zero output rows where mask == 0 -------------
__global__ void __launch_bounds__(256) zero_masked(
    float* __restrict__ out, const int* __restrict__ mask)
{
    const int b = blockIdx.y, s = blockIdx.x;
    if (mask[b * S_ + s]) return;
    float* r = out + ((size_t)b * S_ + s) * D_;
    float4 z = make_float4(0.f, 0.f, 0.f, 0.f);
    *reinterpret_cast<float4*>(r + (threadIdx.x << 2)) = z;
}

extern "C" void kernel_launch(void* const* d_in, const int* in_sizes, int n_in,
                              void* d_out, int out_size)
{
    const float* q    = (const float*)d_in[0];
    const float* kk   = (const float*)d_in[1];
    const float* v    = (const float*)d_in[2];
    const int*   mask = (const int*)  d_in[3];

    float* out = (float*)d_out;                       // output [B,S,D]
    float* aw  = out + (size_t)B_ * S_ * D_;          // attention_weights [B,LQ,S]

    void* p;
    cudaGetSymbolAddress(&p, g_qs);   __half* qs   = (__half*)p;
    cudaGetSymbolAddress(&p, g_ks);   __half* ks   = (__half*)p;
    cudaGetSymbolAddress(&p, g_vts);  __half* vts  = (__half*)p;
    cudaGetSymbolAddress(&p, g_aws);  __half* aws  = (__half*)p;
    cudaGetSymbolAddress(&p, g_awts); __half* awts = (__half*)p;
    cudaGetSymbolAddress(&p, g_o1ts); __half* o1ts = (__half*)p;
    cudaGetSymbolAddress(&p, g_awc);  float* awc  = (float*)p;
    cudaGetSymbolAddress(&p, g_pos);  int*   pos  = (int*)p;
    cudaGetSymbolAddress(&p, g_idx);  int*   idxb = (int*)p;
    cudaGetSymbolAddress(&p, g_scnt); int*   scnt = (int*)p;
    cudaGetSymbolAddress(&p, g_sp);   int*   sp   = (int*)p;

    cudaFuncSetAttribute(gemm_mma<0>, cudaFuncAttributeMaxDynamicSharedMemorySize, SMEM_SZ);
    cudaFuncSetAttribute(gemm_mma<1>, cudaFuncAttributeMaxDynamicSharedMemorySize, SMEM_SZ);
    cudaFuncSetAttribute(gemm_mma<2>, cudaFuncAttributeMaxDynamicSharedMemorySize, SMEM_SZ);

    // 0) mask scan
    scan_mask<<<B_, 256>>>(mask, pos, idxb, scnt, sp);

    // 1) operand prep
    split_rows_q<<<(int)(((size_t)B_ * LQ_ * D_ / 4) / 256), 256>>>(q, qs);
    gather_split_k<<<dim3(S_, B_), 256>>>(kk, ks, idxb, scnt, sp);
    gather_tsplit_v<<<dim3(S_ / 32, D_ / 32, B_), 256>>>(v, vts, idxb, scnt, sp);

    // 2) scores_c = Q @ Kc^T / 32 -> awc  (2-term fp16, N-compact, K=2048)
    gemm_mma<0><<<dim3(S_ / 128, LQ_ / 128, B_), 256, SMEM_SZ>>>(
        qs, ks, awc, nullptr, K2QK, S_,
        (size_t)LQ_ * K2QK, (size_t)S_ * K2QK, (size_t)LQ_ * S_, 0.03125f,
        scnt, sp, idxb);

    // 3) softmax on compacted rows; scatter full aw; fp16 single write
    softmax_compact<<<B_ * LQ_, 256>>>(awc, aw, mask, aws, pos, scnt, sp);

    // 4) awc^T fp16 (compacted rows)
    tsplit_awc<<<dim3(LQ_ / 32, S_ / 32, B_), 256>>>(awc, awts, sp);

    // 5) out1 = awc @ Vc  (single fp16, K = SP) -> o1ts (fp16 transposed epi)
    gemm_mma<1><<<dim3(D_ / 128, LQ_ / 128, B_), 256, SMEM_SZ>>>(
        aws, vts, nullptr, o1ts, KA, 0,
        (size_t)LQ_ * KA, (size_t)D_ * KA, (size_t)D_ * KA, 1.0f,
        scnt, sp, idxb);

    // 6) zero masked output rows; out = awT @ o1 (single fp16, K = LQ), scatter rows
    zero_masked<<<dim3(S_, B_), 256>>>(out, mask);
    gemm_mma<2><<<dim3(D_ / 128, S_ / 128, B_), 256, SMEM_SZ>>>(
        awts, o1ts, out, nullptr, KA, D_,
        (size_t)S_ * KA, (size_t)D_ * KA, (size_t)S_ * D_, 1.0f,
        scnt, sp, idxb);
}

// round 15
// speedup vs baseline: 2.0579x; 1.0204x over previous
#include <cuda_runtime.h>
#include <cuda_fp16.h>
#include <cstdint>

#define B_  16
#define LQ_ 2048
#define S_  2048
#define D_  1024
#define K2QK 2048    // GEMM1 K extent (2-term: Q exact [h|l]; K stored once, wrapped)
#define KA   2048    // GEMM2/3 row pitch (single-term fp16)

// ------------- scratch (__device__ globals = allocation-guard-safe) -------------
static __device__ __half g_qs  [(size_t)B_ * LQ_ * K2QK];  // Q  A-role [h|l] exact
static __device__ __half g_ks  [(size_t)B_ * S_  * D_];    // Kc fp16 single (wrapped by GEMM)
static __device__ __half g_vts [(size_t)B_ * D_  * KA];    // Vc^T fp16 single
static __device__ __half g_aws [(size_t)B_ * LQ_ * KA];    // awc fp16 (probs, compact)
static __device__ __half g_awts[(size_t)B_ * S_  * KA];    // awc^T fp16
static __device__ __half g_o1ts[(size_t)B_ * D_  * KA];    // out1^T fp16
static __device__ float  g_awc [(size_t)B_ * LQ_ * S_];    // compacted raw scores fp32
static __device__ int    g_pos [B_ * S_];
static __device__ int    g_idx [B_ * S_];
static __device__ int    g_scnt[B_];
static __device__ int    g_sp  [B_];

// ------------- PTX helpers -------------
__device__ __forceinline__ uint32_t smem_u32(const void* p) {
    uint32_t a;
    asm("{ .reg .u64 t; cvta.to.shared.u64 t, %1; cvt.u32.u64 %0, t; }" : "=r"(a) : "l"(p));
    return a;
}
#define CP_ASYNC16(dst, src) \
    asm volatile("cp.async.cg.shared.global [%0], [%1], 16;" :: "r"(dst), "l"(src) : "memory")
#define CP_COMMIT() asm volatile("cp.async.commit_group;" ::: "memory")
#define CP_WAIT1()  asm volatile("cp.async.wait_group 1;" ::: "memory")
#define CP_WAIT0()  asm volatile("cp.async.wait_group 0;" ::: "memory")

__device__ __forceinline__ void ldsm_x4(uint32_t& r0, uint32_t& r1, uint32_t& r2,
                                        uint32_t& r3, uint32_t addr) {
    asm volatile("ldmatrix.sync.aligned.m8n8.x4.shared.b16 {%0,%1,%2,%3}, [%4];"
                 : "=r"(r0), "=r"(r1), "=r"(r2), "=r"(r3) : "r"(addr));
}
__device__ __forceinline__ void mma_f16(float* c, uint32_t a0, uint32_t a1,
                                        uint32_t a2, uint32_t a3,
                                        uint32_t b0, uint32_t b1) {
    asm volatile(
        "mma.sync.aligned.m16n8k16.row.col.f32.f16.f16.f32 "
        "{%0,%1,%2,%3}, {%4,%5,%6,%7}, {%8,%9}, {%0,%1,%2,%3};"
        : "+f"(c[0]), "+f"(c[1]), "+f"(c[2]), "+f"(c[3])
        : "r"(a0), "r"(a1), "r"(a2), "r"(a3), "r"(b0), "r"(b1));
}
__device__ __forceinline__ void hsplit(float x, __half& h, __half& l) {
    h = __float2half_rn(x);
    l = __float2half_rn(x - __half2float(h));
}

static constexpr int STAGE   = 32768;
static constexpr int SMEM_SZ = 1024 + 3 * STAGE;

// ------------- mma.sync GEMM: C[M,N] = scale * A[M,K] @ B[N,K]^T -------------
// CTA 128x128, 8 warps 64x32, 64-K chunks, SW128 xor swizzle, 3-stage ring.
// A pitch = ld; B pitch = ldb. MODE 0 wraps the B K-offset modulo D_ (K-dup).
// MODE 0 (G1): N-compact (exit bn>=SP), K = ld (=2048), fp32 C at ldc.
// MODE 1 (G2): K = SP runtime; fp16 transposed epi into Tg pitch KA.
// MODE 2 (G3): M-compact (exit bm>=SP), K = ld (=KA); rows scattered via idx.
template<int MODE>
__global__ void __launch_bounds__(256, 2) gemm_mma(
    const __half* __restrict__ Ag,
    const __half* __restrict__ Bg,
    float* __restrict__ Cg, __half* __restrict__ Tg,
    int ld, int ldb, int ldc, size_t sA, size_t sB, size_t sOut, float scale,
    const int* __restrict__ scnt, const int* __restrict__ sptab,
    const int* __restrict__ idxb)
{
    const int bz = blockIdx.z;
    const int SP = sptab[bz];
    const int bm = blockIdx.y * 128;
    const int bn = blockIdx.x * 128;
    if (MODE == 0 && bn >= SP) return;
    if (MODE == 2 && bm >= SP) return;
    const int K3 = (MODE == 1) ? SP : ld;

    extern __shared__ char dsm[];
    const uint32_t raw  = smem_u32(dsm);
    const uint32_t base = (raw + 1023u) & ~1023u;
    char* sm = dsm + (base - raw);

    const int tid  = threadIdx.x;
    const int wid  = tid >> 5;
    const int lane = tid & 31;
    const __half* A  = Ag + bz * sA;
    const __half* Bp = Bg + bz * sB;

    const int wm = (wid & 1) * 64;
    const int wn = (wid >> 1) * 32;

    float acc[4][4][4];
    #pragma unroll
    for (int i = 0; i < 4; ++i)
        #pragma unroll
        for (int j = 0; j < 4; ++j)
            #pragma unroll
            for (int r = 0; r < 4; ++r) acc[i][j][r] = 0.f;

    const int lr  = tid >> 1;
    const int lc0 = (tid & 1) << 2;
    const int NT  = K3 >> 6;

    auto load_chunk = [&](int kt) {
        const int kc  = kt << 6;
        const int bkc = (MODE == 0) ? (kc & (D_ - 1)) : kc;   // K-dup wrap for G1's B
        const uint32_t ab = base + (kt % 3) * STAGE;
        const uint32_t bb = ab + 16384;
        const __half* arow = A  + (size_t)(bm + lr) * ld  + kc;
        const __half* brow = Bp + (size_t)(bn + lr) * ldb + bkc;
        #pragma unroll
        for (int c = 0; c < 4; ++c) {
            int c16 = lc0 + c;
            uint32_t sw = (uint32_t)((c16 ^ (lr & 7)) << 4);
            CP_ASYNC16(ab + (uint32_t)(lr << 7) + sw, arow + (c16 << 3));
            CP_ASYNC16(bb + (uint32_t)(lr << 7) + sw, brow + (c16 << 3));
        }
        CP_COMMIT();
    };

    load_chunk(0);
    load_chunk(1);

    for (int kt = 0; kt < NT; ++kt) {
        if (kt + 1 < NT) CP_WAIT1();
        else             CP_WAIT0();
        __syncthreads();
        if (kt + 2 < NT) load_chunk(kt + 2);

        const uint32_t ab = base + (kt % 3) * STAGE;
        const uint32_t bb = ab + 16384;
        const int t4 = lane >> 3;

        #pragma unroll
        for (int ks = 0; ks < 4; ++ks) {
            uint32_t Af[4][4];
            #pragma unroll
            for (int mt = 0; mt < 4; ++mt) {
                int row = wm + mt * 16 + ((t4 & 1) << 3) + (lane & 7);
                int c16 = ks * 2 + (t4 >> 1);
                uint32_t addr = ab + (uint32_t)(row << 7)
                              + (uint32_t)((c16 ^ (row & 7)) << 4);
                ldsm_x4(Af[mt][0], Af[mt][1], Af[mt][2], Af[mt][3], addr);
            }
            uint32_t Bf[2][4];
            #pragma unroll
            for (int gt = 0; gt < 2; ++gt) {
                int row = wn + gt * 16 + ((t4 >> 1) << 3) + (lane & 7);
                int c16 = ks * 2 + (t4 & 1);
                uint32_t addr = bb + (uint32_t)(row << 7)
                              + (uint32_t)((c16 ^ (row & 7)) << 4);
                ldsm_x4(Bf[gt][0], Bf[gt][1], Bf[gt][2], Bf[gt][3], addr);
            }
            #pragma unroll
            for (int mt = 0; mt < 4; ++mt)
                #pragma unroll
                for (int ng = 0; ng < 4; ++ng) {
                    const uint32_t* bg = Bf[ng >> 1];
                    mma_f16(acc[mt][ng],
                            Af[mt][0], Af[mt][1], Af[mt][2], Af[mt][3],
                            bg[(ng & 1) * 2], bg[(ng & 1) * 2 + 1]);
                }
        }
    }
    __syncthreads();

    const int qr = lane >> 2;
    const int qc = (lane & 3) << 1;

    if (MODE == 0 || MODE == 2) {
        float* slab = reinterpret_cast<float*>(sm);   // [m][n] pitch 132
        #pragma unroll
        for (int mt = 0; mt < 4; ++mt)
            #pragma unroll
            for (int ng = 0; ng < 4; ++ng) {
                int m = wm + mt * 16 + qr;
                int n = wn + ng * 8 + qc;
                float* p0 = slab + (size_t)m * 132 + n;
                p0[0] = acc[mt][ng][0] * scale;
                p0[1] = acc[mt][ng][1] * scale;
                float* p1 = p0 + 8 * 132;
                p1[0] = acc[mt][ng][2] * scale;
                p1[1] = acc[mt][ng][3] * scale;
            }
        __syncthreads();
        float* Cb = Cg + bz * sOut;
        const int Sc = (MODE == 2) ? scnt[bz] : 0;
        #pragma unroll
        for (int it = 0; it < 16; ++it) {
            int idx = tid + (it << 8);
            int r = idx >> 5, c = (idx & 31) << 2;
            float4 v = *reinterpret_cast<float4*>(slab + (size_t)r * 132 + c);
            if (MODE == 0) {
                *reinterpret_cast<float4*>(Cb + (size_t)(bm + r) * ldc + bn + c) = v;
            } else {
                int gr = bm + r;
                if (gr < Sc) {
                    int trow = idxb[bz * S_ + gr];
                    *reinterpret_cast<float4*>(Cb + (size_t)trow * ldc + bn + c) = v;
                }
            }
        }
    } else {
        float* slab = reinterpret_cast<float*>(sm);   // [n][m] pitch 132
        #pragma unroll
        for (int mt = 0; mt < 4; ++mt)
            #pragma unroll
            for (int ng = 0; ng < 4; ++ng) {
                int m = wm + mt * 16 + qr;
                int n = wn + ng * 8 + qc;
                slab[(size_t)n * 132 + m]           = acc[mt][ng][0];
                slab[(size_t)(n + 1) * 132 + m]     = acc[mt][ng][1];
                slab[(size_t)n * 132 + m + 8]       = acc[mt][ng][2];
                slab[(size_t)(n + 1) * 132 + m + 8] = acc[mt][ng][3];
            }
        __syncthreads();
        __half* T = Tg + bz * sOut;
        #pragma unroll
        for (int it = 0; it < 16; ++it) {
            int idx = tid + (it << 8);
            int n = idx >> 5, mc = (idx & 31) << 2;
            float4 v = *reinterpret_cast<float4*>(slab + (size_t)n * 132 + mc);
            float xs[4] = {v.x, v.y, v.z, v.w};
            __align__(8) __half h[4];
            #pragma unroll
            for (int i = 0; i < 4; ++i) h[i] = __float2half_rn(xs[i]);
            __half* dst = T + (size_t)(bn + n) * KA + bm + mc;
            *reinterpret_cast<uint2*>(dst) = *reinterpret_cast<uint2*>(h);
        }
    }
}

// ------------- mask prefix scan -------------
__global__ void __launch_bounds__(256) scan_mask(
    const int* __restrict__ mask, int* __restrict__ pos, int* __restrict__ idxb,
    int* __restrict__ scnt, int* __restrict__ sptab)
{
    const int b = blockIdx.x;
    const int* mp = mask + b * S_;
    const int t = threadIdx.x;
    __shared__ int part[256];
    int loc[8], sum = 0;
    #pragma unroll
    for (int i = 0; i < 8; ++i) { loc[i] = mp[t * 8 + i]; sum += loc[i]; }
    part[t] = sum;
    __syncthreads();
    for (int off = 1; off < 256; off <<= 1) {
        int v = (t >= off) ? part[t - off] : 0;
        __syncthreads();
        part[t] += v;
        __syncthreads();
    }
    int run = part[t] - sum;
    #pragma unroll
    for (int i = 0; i < 8; ++i) {
        int s = t * 8 + i;
        pos[b * S_ + s] = run;
        if (loc[i]) { idxb[b * S_ + run] = s; ++run; }
    }
    if (t == 255) {
        scnt[b]  = run;
        sptab[b] = (run + 127) & ~127;
    }
}

// ------------- Q split A-role [h|l] exact, pitch 2048 -------------
__global__ void __launch_bounds__(256) split_rows_q(
    const float* __restrict__ in, __half* __restrict__ out)
{
    size_t idx = (size_t)blockIdx.x * 256 + threadIdx.x;
    size_t row = idx >> 8;
    int    c   = (int)(idx & 255) << 2;
    float4 v = *reinterpret_cast<const float4*>(in + row * D_ + c);
    float xs[4] = {v.x, v.y, v.z, v.w};
    __align__(8) __half h[4], l[4];
    #pragma unroll
    for (int i = 0; i < 4; ++i) hsplit(xs[i], h[i], l[i]);
    __half* o = out + row * (size_t)K2QK + c;
    *reinterpret_cast<uint2*>(o)      = *reinterpret_cast<uint2*>(h);
    *reinterpret_cast<uint2*>(o + D_) = *reinterpret_cast<uint2*>(l);
}

// ------------- K gather fp16 single, pitch D_ (GEMM wraps for dup) -------------
__global__ void __launch_bounds__(256) gather_split_k(
    const float* __restrict__ k, __half* __restrict__ out,
    const int* __restrict__ idxb, const int* __restrict__ scnt,
    const int* __restrict__ sptab)
{
    const int b = blockIdx.y, j = blockIdx.x;
    if (j >= sptab[b]) return;
    const int t = threadIdx.x, c = t << 2;
    __half* o = out + ((size_t)b * S_ + j) * D_ + c;
    __align__(8) __half h[4];
    if (j < scnt[b]) {
        const float* src = k + ((size_t)b * S_ + idxb[b * S_ + j]) * D_ + c;
        float4 v = *reinterpret_cast<const float4*>(src);
        float xs[4] = {v.x, v.y, v.z, v.w};
        #pragma unroll
        for (int i = 0; i < 4; ++i) h[i] = __float2half_rn(xs[i]);
    } else {
        #pragma unroll
        for (int i = 0; i < 4; ++i) h[i] = __float2half_rn(0.f);
    }
    *reinterpret_cast<uint2*>(o) = *reinterpret_cast<uint2*>(h);
}

// ------------- V gather + transpose, fp16 single, pitch KA -------------
__global__ void __launch_bounds__(256) gather_tsplit_v(
    const float* __restrict__ v, __half* __restrict__ out,
    const int* __restrict__ idxb, const int* __restrict__ scnt,
    const int* __restrict__ sptab)
{
    const int b  = blockIdx.z;
    const int SP = sptab[b], Sc = scnt[b];
    const int j0 = blockIdx.x * 32;
    if (j0 >= SP) return;
    const int d0 = blockIdx.y * 32;
    const float* ip = v + (size_t)b * S_ * D_;
    __half* op = out + (size_t)b * D_ * KA;
    __shared__ float tile[32][33];
    const int tx = threadIdx.x & 31, ty = threadIdx.x >> 5;
    #pragma unroll
    for (int i = 0; i < 4; ++i) {
        int jr = j0 + ty + i * 8;
        float val = 0.f;
        if (jr < Sc) val = ip[(size_t)idxb[b * S_ + jr] * D_ + d0 + tx];
        tile[ty + i * 8][tx] = val;
    }
    __syncthreads();
    #pragma unroll
    for (int i = 0; i < 4; ++i) {
        int cc = ty + i * 8;
        op[(size_t)(d0 + cc) * KA + j0 + tx] = __float2half_rn(tile[tx][cc]);
    }
}

// ------------- softmax compact + full-aw scatter + fp16 prob write -------------
__global__ void __launch_bounds__(256) softmax_compact(
    const float* __restrict__ awc, float* __restrict__ aw, const int* __restrict__ mask,
    __half* __restrict__ aws, const int* __restrict__ pos,
    const int* __restrict__ scnt, const int* __restrict__ sptab)
{
    const int row = blockIdx.x;
    const int b   = row >> 11;
    const int Sc  = scnt[b], SP = sptab[b];
    const float* cp = awc + (size_t)row * S_;
    float*       rp = aw  + (size_t)row * S_;
    __half*      ap = aws + (size_t)row * KA;
    const int*   mp = mask + b * S_;
    const int*   pp = pos  + b * S_;
    const int t = threadIdx.x;
    const float NEG_INF = __int_as_float(0xff800000);

    __shared__ float parr[2048];
    __shared__ float smax[8], ssum[8];

    float vv[8];
    float mx = NEG_INF;
    #pragma unroll
    for (int i = 0; i < 8; ++i) {
        int j = t + (i << 8);
        vv[i] = (j < Sc) ? cp[j] : NEG_INF;
        mx = fmaxf(mx, vv[i]);
    }
    #pragma unroll
    for (int off = 16; off > 0; off >>= 1)
        mx = fmaxf(mx, __shfl_xor_sync(0xffffffffu, mx, off));
    if ((t & 31) == 0) smax[t >> 5] = mx;
    __syncthreads();
    float rmax = smax[0];
    #pragma unroll
    for (int i = 1; i < 8; ++i) rmax = fmaxf(rmax, smax[i]);

    float e[8], sum = 0.f;
    #pragma unroll
    for (int i = 0; i < 8; ++i) {
        int j = t + (i << 8);
        e[i] = (j < Sc) ? __expf(vv[i] - rmax) : 0.f;
        sum += e[i];
    }
    #pragma unroll
    for (int off = 16; off > 0; off >>= 1)
        sum += __shfl_xor_sync(0xffffffffu, sum, off);
    if ((t & 31) == 0) ssum[t >> 5] = sum;
    __syncthreads();
    float rsum = 0.f;
    #pragma unroll
    for (int i = 0; i < 8; ++i) rsum += ssum[i];
    const float inv = 1.f / rsum;

    #pragma unroll
    for (int i = 0; i < 8; ++i) {
        int j = t + (i << 8);
        if (j < SP) {
            float p = e[i] * inv;          // 0 for j >= Sc
            parr[j] = p;
            ap[j]   = __float2half_rn(p);
        }
    }
    __syncthreads();
    #pragma unroll
    for (int i = 0; i < 8; ++i) {
        int s = t + (i << 8);
        rp[s] = mp[s] ? parr[pp[s]] : 0.f;
    }
}

// ------------- transpose aws (fp16 probs) -> awts fp16, pitch KA -------------
__global__ void __launch_bounds__(256) tsplit_awc(
    const __half* __restrict__ aws, __half* __restrict__ out,
    const int* __restrict__ sptab)
{
    const int b  = blockIdx.z;
    const int c0 = blockIdx.y * 32;
    if (c0 >= sptab[b]) return;
    const int r0 = blockIdx.x * 32;
    const __half* ip = aws + (size_t)b * LQ_ * KA;
    __half* op = out + (size_t)b * S_ * KA;
    __shared__ __half tile[32][34];
    const int tx = threadIdx.x & 31, ty = threadIdx.x >> 5;
    #pragma unroll
    for (int i = 0; i < 4; ++i)
        tile[ty + i * 8][tx] = ip[(size_t)(r0 + ty + i * 8) * KA + c0 + tx];
    __syncthreads();
    #pragma unroll
    for (int i = 0; i < 4; ++i) {
        int cc = ty + i * 8;
        op[(size_t)(c0 + cc) * KA + r0 + tx] = tile[tx][cc];
    }
}

// ------------- zero output rows where mask == 0 -------------
__global__ void __launch_bounds__(256) zero_masked(
    float* __restrict__ out, const int* __restrict__ mask)
{
    const int b = blockIdx.y, s = blockIdx.x;
    if (mask[b * S_ + s]) return;
    float* r = out + ((size_t)b * S_ + s) * D_;
    float4 z = make_float4(0.f, 0.f, 0.f, 0.f);
    *reinterpret_cast<float4*>(r + (threadIdx.x << 2)) = z;
}

extern "C" void kernel_launch(void* const* d_in, const int* in_sizes, int n_in,
                              void* d_out, int out_size)
{
    const float* q    = (const float*)d_in[0];
    const float* kk   = (const float*)d_in[1];
    const float* v    = (const float*)d_in[2];
    const int*   mask = (const int*)  d_in[3];

    float* out = (float*)d_out;                       // output [B,S,D]
    float* aw  = out + (size_t)B_ * S_ * D_;          // attention_weights [B,LQ,S]

    void* p;
    cudaGetSymbolAddress(&p, g_qs);   __half* qs   = (__half*)p;
    cudaGetSymbolAddress(&p, g_ks);   __half* ks   = (__half*)p;
    cudaGetSymbolAddress(&p, g_vts);  __half* vts  = (__half*)p;
    cudaGetSymbolAddress(&p, g_aws);  __half* aws  = (__half*)p;
    cudaGetSymbolAddress(&p, g_awts); __half* awts = (__half*)p;
    cudaGetSymbolAddress(&p, g_o1ts); __half* o1ts = (__half*)p;
    cudaGetSymbolAddress(&p, g_awc);  float* awc  = (float*)p;
    cudaGetSymbolAddress(&p, g_pos);  int*   pos  = (int*)p;
    cudaGetSymbolAddress(&p, g_idx);  int*   idxb = (int*)p;
    cudaGetSymbolAddress(&p, g_scnt); int*   scnt = (int*)p;
    cudaGetSymbolAddress(&p, g_sp);   int*   sp   = (int*)p;

    cudaFuncSetAttribute(gemm_mma<0>, cudaFuncAttributeMaxDynamicSharedMemorySize, SMEM_SZ);
    cudaFuncSetAttribute(gemm_mma<1>, cudaFuncAttributeMaxDynamicSharedMemorySize, SMEM_SZ);
    cudaFuncSetAttribute(gemm_mma<2>, cudaFuncAttributeMaxDynamicSharedMemorySize, SMEM_SZ);

    // 0) mask scan
    scan_mask<<<B_, 256>>>(mask, pos, idxb, scnt, sp);

    // 1) operand prep
    split_rows_q<<<(int)(((size_t)B_ * LQ_ * D_ / 4) / 256), 256>>>(q, qs);
    gather_split_k<<<dim3(S_, B_), 256>>>(kk, ks, idxb, scnt, sp);
    gather_tsplit_v<<<dim3(S_ / 32, D_ / 32, B_), 256>>>(v, vts, idxb, scnt, sp);

    // 2) scores_c = Q @ Kc^T / 32 -> awc  (2-term fp16: K buffer wrapped, K=2048)
    gemm_mma<0><<<dim3(S_ / 128, LQ_ / 128, B_), 256, SMEM_SZ>>>(
        qs, ks, awc, nullptr, K2QK, D_, S_,
        (size_t)LQ_ * K2QK, (size_t)S_ * D_, (size_t)LQ_ * S_, 0.03125f,
        scnt, sp, idxb);

    // 3) softmax on compacted rows; scatter full aw; fp16 prob write (aws)
    softmax_compact<<<B_ * LQ_, 256>>>(awc, aw, mask, aws, pos, scnt, sp);

    // 4) awts = transpose(aws)  (fp16 -> fp16)
    tsplit_awc<<<dim3(LQ_ / 32, S_ / 32, B_), 256>>>(aws, awts, sp);

    // 5) out1 = aws @ Vc  (K = SP) -> o1ts (fp16 transposed epi)
    gemm_mma<1><<<dim3(D_ / 128, LQ_ / 128, B_), 256, SMEM_SZ>>>(
        aws, vts, nullptr, o1ts, KA, KA, 0,
        (size_t)LQ_ * KA, (size_t)D_ * KA, (size_t)D_ * KA, 1.0f,
        scnt, sp, idxb);

    // 6) zero masked output rows; out = awts @ o1ts (K = LQ), scatter rows
    zero_masked<<<dim3(S_, B_), 256>>>(out, mask);
    gemm_mma<2><<<dim3(D_ / 128, S_ / 128, B_), 256, SMEM_SZ>>>(
        awts, o1ts, out, nullptr, KA, KA, D_,
        (size_t)S_ * KA, (size_t)D_ * KA, (size_t)S_ * D_, 1.0f,
        scnt, sp, idxb);
}